// round 6
// baseline (speedup 1.0000x reference)
#include <cuda_runtime.h>
#include <cuda_bf16.h>
#include <math.h>
#include <stdint.h>

// ---------------- problem constants ----------------
#define BATCH 2048
#define LD    100
#define DIM   128
#define L1O   97
#define L2O   92
#define L3O   85

typedef __nv_bfloat16 bf16;

#define H2ELEMS (BATCH * L2O * 256)   // 48,234,496

// ---------------- scratch (device globals; allocation-free) ----------------
__device__ bf16 g_xh [BATCH * LD  * DIM];   __device__ bf16 g_xl [BATCH * LD  * DIM];
__device__ bf16 g_h1h[BATCH * L1O * 128];   __device__ bf16 g_h1l[BATCH * L1O * 128];
__device__ bf16 g_h2h[H2ELEMS];             __device__ bf16 g_h2l[H2ELEMS];
__device__ bf16 g_dch[BATCH * L3O * 512];   __device__ bf16 g_dcl[BATCH * L3O * 512];
__device__ bf16 g_atth[BATCH * L3O * 512];  __device__ bf16 g_attl[BATCH * L3O * 512];
__device__ bf16 g_hf1h[BATCH * 128];        __device__ bf16 g_hf1l[BATCH * 128];
__device__ bf16 g_hf2h[BATCH * 256];        __device__ bf16 g_hf2l[BATCH * 256];
__device__ bf16 g_fnnh[BATCH * 512];        __device__ bf16 g_fnnl[BATCH * 512];
__device__ bf16 g_pairh[BATCH * 1024];      __device__ bf16 g_pairl[BATCH * 1024];
__device__ bf16 g_fh1h[BATCH * 1024];       __device__ bf16 g_fh1l[BATCH * 1024];
__device__ bf16 g_fh2h[BATCH * 1024];       __device__ bf16 g_fh2l[BATCH * 1024];
__device__ float g_Amf[BATCH * L3O * 512];
__device__ float g_fattf[BATCH * 512];
__device__ float g_fh3f[BATCH * 512];
__device__ float g_fwm1[128 * 7];
__device__ bf16 g_w1rh[128 * 512];   __device__ bf16 g_w1rl[128 * 512];
__device__ bf16 g_w2rh[256 * 768];   __device__ bf16 g_w2rl[256 * 768];
__device__ bf16 g_fwm2h[256 * 128];  __device__ bf16 g_fwm2l[256 * 128];
__device__ bf16 g_fwm3h[512 * 256];  __device__ bf16 g_fwm3l[512 * 256];
__device__ bf16 g_Wdah[512 * 512];   __device__ bf16 g_Wdal[512 * 512];
__device__ bf16 g_Wfah[512 * 512];   __device__ bf16 g_Wfal[512 * 512];
__device__ bf16 g_Watth[512 * 512];  __device__ bf16 g_Wattl[512 * 512];
__device__ bf16 g_W1h[1024 * 1024];  __device__ bf16 g_W1l[1024 * 1024];
__device__ bf16 g_W2h[1024 * 1024];  __device__ bf16 g_W2l[1024 * 1024];
__device__ bf16 g_W3h[512 * 1024];   __device__ bf16 g_W3l[512 * 1024];
// int8 path (conv3)
__device__ unsigned g_h2maxbits;
__device__ int8_t g_h2q1[H2ELEMS];
__device__ int8_t g_h2q2[H2ELEMS];
__device__ int8_t g_w3q1[512 * 2048];
__device__ int8_t g_w3q2[512 * 2048];
__device__ float  g_w3s[512];

// ---------------- helpers ----------------
__device__ __forceinline__ uint32_t smem_u32(const void* p) {
    uint32_t a;
    asm("{ .reg .u64 t; cvta.to.shared.u64 t, %1; cvt.u32.u64 %0, t; }"
        : "=r"(a) : "l"(p));
    return a;
}
__device__ __forceinline__ void ldm4(uint32_t* r, uint32_t saddr) {
    asm volatile("ldmatrix.sync.aligned.m8n8.x4.shared.b16 {%0,%1,%2,%3}, [%4];"
        : "=r"(r[0]), "=r"(r[1]), "=r"(r[2]), "=r"(r[3]) : "r"(saddr));
}
__device__ __forceinline__ void mma16816(float* d, const uint32_t* a,
                                         uint32_t b0, uint32_t b1) {
    asm volatile(
        "mma.sync.aligned.m16n8k16.row.col.f32.bf16.bf16.f32 "
        "{%0,%1,%2,%3}, {%4,%5,%6,%7}, {%8,%9}, {%0,%1,%2,%3};"
        : "+f"(d[0]), "+f"(d[1]), "+f"(d[2]), "+f"(d[3])
        : "r"(a[0]), "r"(a[1]), "r"(a[2]), "r"(a[3]), "r"(b0), "r"(b1));
}
__device__ __forceinline__ void immak32(int* d, const uint32_t* a,
                                        uint32_t b0, uint32_t b1) {
    asm volatile(
        "mma.sync.aligned.m16n8k32.row.col.s32.s8.s8.s32 "
        "{%0,%1,%2,%3}, {%4,%5,%6,%7}, {%8,%9}, {%0,%1,%2,%3};"
        : "+r"(d[0]), "+r"(d[1]), "+r"(d[2]), "+r"(d[3])
        : "r"(a[0]), "r"(a[1]), "r"(a[2]), "r"(a[3]), "r"(b0), "r"(b1));
}
#define CPA16(dst, src) \
    asm volatile("cp.async.cg.shared.global [%0], [%1], 16;" :: "r"(dst), "l"(src) : "memory")
#define CPCOMMIT() asm volatile("cp.async.commit_group;" ::: "memory")
template <int NW> __device__ __forceinline__ void cpwait() {
    asm volatile("cp.async.wait_group %0;" :: "n"(NW) : "memory");
}
__device__ __forceinline__ uint32_t pack2(float x, float y) {
    bf16 a = __float2bfloat16(x), b = __float2bfloat16(y);
    return (uint32_t)__bfloat16_as_ushort(a) | ((uint32_t)__bfloat16_as_ushort(b) << 16);
}
__device__ __forceinline__ float bf16lo_res(float x) {
    return x - __bfloat162float(__float2bfloat16(x));
}
__device__ __forceinline__ void split1(float v, bf16& h, bf16& l) {
    h = __float2bfloat16(v);
    l = __float2bfloat16(v - __bfloat162float(h));
}

// ---------------- bf16 GEMM (unchanged from R5) ----------------
#define ROWB   80u
#define AREG   20480u
#define BREG   10240u
#define STG    61440u
#define GSMEM  (2 * 61440)

template <int ACT, int OM>
__global__ __launch_bounds__(256, 1)
void gemm2(const bf16* __restrict__ Ah, const bf16* __restrict__ Al,
           const bf16* __restrict__ Wh, const bf16* __restrict__ Wl,
           const float* __restrict__ bias, const float* __restrict__ extra,
           float* __restrict__ Cf, bf16* __restrict__ Ch, bf16* __restrict__ Cl,
           int N, int K, int Lout, long sOuter, long sInner, int rowdiv) {
    extern __shared__ char sm[];
    const uint32_t smb = smem_u32(sm);
    const int tid = threadIdx.x;
    const int wid = tid >> 5, lane = tid & 31;
    const int m0 = blockIdx.y * 256, n0 = blockIdx.x * 128;
    const int wm = wid >> 1, wn = wid & 1;

    const int mrow = m0 + tid;
    const long aoff = (long)(mrow / Lout) * sOuter + (long)(mrow % Lout) * sInner;
    const bf16* aH = Ah + aoff;
    const bf16* aL = Al + aoff;
    const int brow = n0 + (tid >> 1);
    const bf16* bH = Wh + (long)brow * K;
    const bf16* bL = Wl + (long)brow * K;
    const int bseg = (tid & 1) * 2;

    const uint32_t aDst = smb + (uint32_t)tid * ROWB;
    const uint32_t bDst = smb + 2u * AREG + (uint32_t)(tid >> 1) * ROWB + (uint32_t)bseg * 16u;

    const int laneR = lane & 15;
    const uint32_t laneC = (uint32_t)(lane >> 4) * 16u;
    const uint32_t aBase = smb + (uint32_t)(wm * 64 + laneR) * ROWB + laneC;
    const uint32_t bBase = smb + 2u * AREG + (uint32_t)(wn * 64 + laneR) * ROWB + laneC;

    float acc[4][8][4];
#pragma unroll
    for (int i = 0; i < 4; i++)
#pragma unroll
        for (int j = 0; j < 8; j++)
#pragma unroll
            for (int k = 0; k < 4; k++) acc[i][j][k] = 0.f;

    const int T = K / 32;
    {
#pragma unroll
        for (int s = 0; s < 4; s++) CPA16(aDst + s * 16u, aH + s * 8);
#pragma unroll
        for (int s = 0; s < 4; s++) CPA16(aDst + AREG + s * 16u, aL + s * 8);
#pragma unroll
        for (int s = 0; s < 2; s++) CPA16(bDst + s * 16u, bH + (bseg + s) * 8);
#pragma unroll
        for (int s = 0; s < 2; s++) CPA16(bDst + BREG + s * 16u, bL + (bseg + s) * 8);
        CPCOMMIT();
    }

    for (int t = 0; t < T; ++t) {
        if (t + 1 < T) {
            const int k0 = (t + 1) * 32;
            const uint32_t sb = (uint32_t)((t + 1) & 1) * STG;
#pragma unroll
            for (int s = 0; s < 4; s++) CPA16(aDst + sb + s * 16u, aH + k0 + s * 8);
#pragma unroll
            for (int s = 0; s < 4; s++) CPA16(aDst + sb + AREG + s * 16u, aL + k0 + s * 8);
#pragma unroll
            for (int s = 0; s < 2; s++) CPA16(bDst + sb + s * 16u, bH + k0 + (bseg + s) * 8);
#pragma unroll
            for (int s = 0; s < 2; s++) CPA16(bDst + sb + BREG + s * 16u, bL + k0 + (bseg + s) * 8);
            CPCOMMIT();
            cpwait<1>();
        } else {
            cpwait<0>();
        }
        __syncthreads();

        const uint32_t soff = (uint32_t)(t & 1) * STG;
#pragma unroll
        for (int j = 0; j < 2; j++) {
            const uint32_t ja = soff + (uint32_t)j * 32u;
            uint32_t ah[4][4], al[4][4], bh[4][4], bl[4][4];
#pragma unroll
            for (int mt = 0; mt < 4; mt++) {
                ldm4(ah[mt], aBase + ja + (uint32_t)mt * (16u * ROWB));
                ldm4(al[mt], aBase + ja + (uint32_t)mt * (16u * ROWB) + AREG);
            }
#pragma unroll
            for (int nt = 0; nt < 4; nt++) {
                ldm4(bh[nt], bBase + ja + (uint32_t)nt * (16u * ROWB));
                ldm4(bl[nt], bBase + ja + (uint32_t)nt * (16u * ROWB) + BREG);
            }
#pragma unroll
            for (int nt = 0; nt < 4; nt++)
#pragma unroll
                for (int mt = 0; mt < 4; mt++) {
                    mma16816(acc[mt][2 * nt],     ah[mt], bh[nt][0], bh[nt][2]);
                    mma16816(acc[mt][2 * nt + 1], ah[mt], bh[nt][1], bh[nt][3]);
                }
#pragma unroll
            for (int nt = 0; nt < 4; nt++)
#pragma unroll
                for (int mt = 0; mt < 4; mt++) {
                    mma16816(acc[mt][2 * nt],     al[mt], bh[nt][0], bh[nt][2]);
                    mma16816(acc[mt][2 * nt + 1], al[mt], bh[nt][1], bh[nt][3]);
                }
#pragma unroll
            for (int nt = 0; nt < 4; nt++)
#pragma unroll
                for (int mt = 0; mt < 4; mt++) {
                    mma16816(acc[mt][2 * nt],     ah[mt], bl[nt][0], bl[nt][2]);
                    mma16816(acc[mt][2 * nt + 1], ah[mt], bl[nt][1], bl[nt][3]);
                }
        }
        __syncthreads();
    }

    const int lr2 = lane >> 2;
    const int lc2 = (lane & 3) * 2;
#pragma unroll
    for (int mt = 0; mt < 4; mt++) {
#pragma unroll
        for (int h = 0; h < 2; h++) {
            const long m = (long)m0 + wm * 64 + mt * 16 + h * 8 + lr2;
            const long rowb = m * (long)N;
            const float* erow = (ACT == 3) ? (extra + (long)(m / rowdiv) * N) : nullptr;
#pragma unroll
            for (int nt2 = 0; nt2 < 8; nt2++) {
                const int n = n0 + wn * 64 + nt2 * 8 + lc2;
                float vx = acc[mt][nt2][2 * h]     + bias[n];
                float vy = acc[mt][nt2][2 * h + 1] + bias[n + 1];
                if (ACT == 3) { vx += erow[n]; vy += erow[n + 1]; }
                if (ACT == 1 || ACT == 3) {
                    vx = fmaxf(vx, 0.f); vy = fmaxf(vy, 0.f);
                } else if (ACT == 2) {
                    vx = vx > 0.f ? vx : 0.01f * vx;
                    vy = vy > 0.f ? vy : 0.01f * vy;
                }
                if (OM == 0)
                    *(float2*)(Cf + rowb + n) = make_float2(vx, vy);
                else {
                    *(uint32_t*)(Ch + rowb + n) = pack2(vx, vy);
                    *(uint32_t*)(Cl + rowb + n) = pack2(bf16lo_res(vx), bf16lo_res(vy));
                }
            }
        }
    }
}

// ---------------- int8 GEMM for conv3 ----------------
// CTA 128x128, 8 warps (4m x 2n), warp 32x64. K=2048 staged by 64 bytes.
// D = sA*sW[n]/16129 * (P1 + Pc/254); P1 = a1*b1, Pc = a1*b2 + a2*b1.
#define I8ROWB  80u
#define I8PLANE 10240u          // 128 rows * 80B
#define I8STG   40960u          // 4 planes
#define I8SMEM  (2 * 40960)

__global__ __launch_bounds__(256, 1)
void gemm_i8_conv3(const int8_t* __restrict__ Aq1, const int8_t* __restrict__ Aq2,
                   const int8_t* __restrict__ Wq1, const int8_t* __restrict__ Wq2,
                   const float* __restrict__ wS, const unsigned* __restrict__ aMaxBits,
                   const float* __restrict__ bias,
                   bf16* __restrict__ Ch, bf16* __restrict__ Cl) {
    extern __shared__ char sm[];
    const uint32_t smb = smem_u32(sm);
    const int tid = threadIdx.x;
    const int wid = tid >> 5, lane = tid & 31;
    const int m0 = blockIdx.y * 128, n0 = blockIdx.x * 128;
    const int wm = wid >> 1, wn = wid & 1;
    const int N = 512, K = 2048;

    // loader: row r = tid>>1, chunks (tid&1)*2 + {0,1}
    const int lrow = tid >> 1;
    const int lch  = (tid & 1) * 2;
    const int am = m0 + lrow;
    const long abase = ((long)(am / L3O) * L2O + (am % L3O)) * 256;
    const int8_t* a1p = Aq1 + abase;
    const int8_t* a2p = Aq2 + abase;
    const int8_t* b1p = Wq1 + (long)(n0 + lrow) * K;
    const int8_t* b2p = Wq2 + (long)(n0 + lrow) * K;
    const uint32_t rowDst = smb + (uint32_t)lrow * I8ROWB + (uint32_t)lch * 16u;

    // ldmatrix bases
    const uint32_t aLC = (uint32_t)(lane >> 4) * 16u;
    const uint32_t aBase = smb + (uint32_t)(wm * 32 + (lane & 15)) * I8ROWB + aLC;
    const uint32_t bRow = (uint32_t)((lane & 7) + ((lane >> 4) << 3));
    const uint32_t bLC  = (uint32_t)((lane >> 3) & 1) * 16u;
    const uint32_t bBase = smb + 2u * I8PLANE + ((uint32_t)(wn * 64) + bRow) * I8ROWB + bLC;

    int acc1[2][8][4], acc2[2][8][4];
#pragma unroll
    for (int i = 0; i < 2; i++)
#pragma unroll
        for (int j = 0; j < 8; j++)
#pragma unroll
            for (int k = 0; k < 4; k++) { acc1[i][j][k] = 0; acc2[i][j][k] = 0; }

    const int T = K / 64;   // 32 stages
    {
#pragma unroll
        for (int s = 0; s < 2; s++) {
            CPA16(rowDst + s * 16u,                 a1p + (lch + s) * 16);
            CPA16(rowDst + I8PLANE + s * 16u,       a2p + (lch + s) * 16);
            CPA16(rowDst + 2u * I8PLANE + s * 16u,  b1p + (lch + s) * 16);
            CPA16(rowDst + 3u * I8PLANE + s * 16u,  b2p + (lch + s) * 16);
        }
        CPCOMMIT();
    }

    for (int t = 0; t < T; ++t) {
        if (t + 1 < T) {
            const int k0 = (t + 1) * 64;
            const uint32_t sb = (uint32_t)((t + 1) & 1) * I8STG;
#pragma unroll
            for (int s = 0; s < 2; s++) {
                CPA16(rowDst + sb + s * 16u,                a1p + k0 + (lch + s) * 16);
                CPA16(rowDst + sb + I8PLANE + s * 16u,      a2p + k0 + (lch + s) * 16);
                CPA16(rowDst + sb + 2u * I8PLANE + s * 16u, b1p + k0 + (lch + s) * 16);
                CPA16(rowDst + sb + 3u * I8PLANE + s * 16u, b2p + k0 + (lch + s) * 16);
            }
            CPCOMMIT();
            cpwait<1>();
        } else {
            cpwait<0>();
        }
        __syncthreads();

        const uint32_t soff = (uint32_t)(t & 1) * I8STG;
#pragma unroll
        for (int j = 0; j < 2; j++) {             // two k32 steps
            const uint32_t ja = soff + (uint32_t)j * 32u;
            uint32_t a1f[2][4], a2f[2][4], b1f[4][4], b2f[4][4];
#pragma unroll
            for (int mt = 0; mt < 2; mt++) {
                ldm4(a1f[mt], aBase + ja + (uint32_t)mt * (16u * I8ROWB));
                ldm4(a2f[mt], aBase + ja + (uint32_t)mt * (16u * I8ROWB) + I8PLANE);
            }
#pragma unroll
            for (int g = 0; g < 4; g++) {          // each covers 2 n8-tiles
                ldm4(b1f[g], bBase + ja + (uint32_t)g * (16u * I8ROWB));
                ldm4(b2f[g], bBase + ja + (uint32_t)g * (16u * I8ROWB) + I8PLANE);
            }
            // P1 = a1*b1
#pragma unroll
            for (int g = 0; g < 4; g++)
#pragma unroll
                for (int mt = 0; mt < 2; mt++) {
                    immak32(acc1[mt][2 * g],     a1f[mt], b1f[g][0], b1f[g][1]);
                    immak32(acc1[mt][2 * g + 1], a1f[mt], b1f[g][2], b1f[g][3]);
                }
            // Pc += a1*b2
#pragma unroll
            for (int g = 0; g < 4; g++)
#pragma unroll
                for (int mt = 0; mt < 2; mt++) {
                    immak32(acc2[mt][2 * g],     a1f[mt], b2f[g][0], b2f[g][1]);
                    immak32(acc2[mt][2 * g + 1], a1f[mt], b2f[g][2], b2f[g][3]);
                }
            // Pc += a2*b1
#pragma unroll
            for (int g = 0; g < 4; g++)
#pragma unroll
                for (int mt = 0; mt < 2; mt++) {
                    immak32(acc2[mt][2 * g],     a2f[mt], b1f[g][0], b1f[g][1]);
                    immak32(acc2[mt][2 * g + 1], a2f[mt], b1f[g][2], b1f[g][3]);
                }
        }
        __syncthreads();
    }

    // epilogue
    const float sA = __uint_as_float(*aMaxBits);
    const float s0 = sA * (1.0f / 16129.0f);
    const int lr2 = lane >> 2;
    const int lc2 = (lane & 3) * 2;
#pragma unroll
    for (int mt = 0; mt < 2; mt++) {
#pragma unroll
        for (int h = 0; h < 2; h++) {
            const long m = (long)m0 + wm * 32 + mt * 16 + h * 8 + lr2;
            const long rowb = m * (long)N;
#pragma unroll
            for (int nt = 0; nt < 8; nt++) {
                const int n = n0 + wn * 64 + nt * 8 + lc2;
                const float sx = s0 * wS[n], sy = s0 * wS[n + 1];
                float vx = ((float)acc1[mt][nt][2 * h]
                           + (float)acc2[mt][nt][2 * h] * (1.0f / 254.0f)) * sx + bias[n];
                float vy = ((float)acc1[mt][nt][2 * h + 1]
                           + (float)acc2[mt][nt][2 * h + 1] * (1.0f / 254.0f)) * sy + bias[n + 1];
                vx = fmaxf(vx, 0.f); vy = fmaxf(vy, 0.f);
                *(uint32_t*)(Ch + rowb + n) = pack2(vx, vy);
                *(uint32_t*)(Cl + rowb + n) = pack2(bf16lo_res(vx), bf16lo_res(vy));
            }
        }
    }
}

// ---------------- quantization kernels ----------------
__global__ void reset_k(unsigned* mb) { if (threadIdx.x == 0) *mb = 0; }

__global__ void absmax_k(const bf16* __restrict__ x, int total, unsigned* mb) {
    int idx = blockIdx.x * blockDim.x + threadIdx.x;
    float m = 0.f;
    for (int i = idx; i < total; i += gridDim.x * blockDim.x)
        m = fmaxf(m, __bfloat162float(x[i]));   // post-relu: >= 0
#pragma unroll
    for (int o = 16; o > 0; o >>= 1) m = fmaxf(m, __shfl_xor_sync(0xffffffffu, m, o));
    __shared__ float red[8];
    if ((threadIdx.x & 31) == 0) red[threadIdx.x >> 5] = m;
    __syncthreads();
    if (threadIdx.x == 0) {
        float bm = red[0];
#pragma unroll
        for (int i = 1; i < 8; i++) bm = fmaxf(bm, red[i]);
        bm = fmaxf(bm, 1e-30f);
        atomicMax(mb, __float_as_uint(bm));
    }
}

__global__ void quant_k(const bf16* __restrict__ xh, const bf16* __restrict__ xl,
                        const unsigned* __restrict__ mb, int total,
                        int8_t* __restrict__ q1, int8_t* __restrict__ q2) {
    int idx = blockIdx.x * blockDim.x + threadIdx.x;
    if (idx >= total) return;
    const float r127 = 127.0f / __uint_as_float(*mb);
    float x = __bfloat162float(xh[idx]) + __bfloat162float(xl[idx]);
    float v = fminf(x * r127, 127.4f);
    float d1 = rintf(v);
    float d2 = fminf(fmaxf(rintf((v - d1) * 254.0f), -127.f), 127.f);
    q1[idx] = (int8_t)(int)d1;
    q2[idx] = (int8_t)(int)d2;
}

// reorder + row-quantize dw3[o][i][k] -> wq[o][k*256+i], per-row scale
__global__ void w3quant_k(const float* __restrict__ w,
                          int8_t* __restrict__ q1, int8_t* __restrict__ q2,
                          float* __restrict__ ws) {
    const int o = blockIdx.x;           // 512 rows
    const int tid = threadIdx.x;        // 256 threads
    __shared__ float red[8];
    float m = 0.f;
    for (int kk = tid; kk < 2048; kk += 256) {
        int i = kk & 255, k = kk >> 8;
        m = fmaxf(m, fabsf(w[((size_t)o * 256 + i) * 8 + k]));
    }
#pragma unroll
    for (int s = 16; s > 0; s >>= 1) m = fmaxf(m, __shfl_xor_sync(0xffffffffu, m, s));
    if ((tid & 31) == 0) red[tid >> 5] = m;
    __syncthreads();
    float bm = fmaxf(red[0], 1e-30f);
#pragma unroll
    for (int i = 1; i < 8; i++) bm = fmaxf(bm, red[i]);
    const float r127 = 127.0f / bm;
    for (int kk = tid; kk < 2048; kk += 256) {
        int i = kk & 255, k = kk >> 8;
        float v = w[((size_t)o * 256 + i) * 8 + k] * r127;
        v = fminf(fmaxf(v, -127.4f), 127.4f);
        float d1 = rintf(v);
        float d2 = fminf(fmaxf(rintf((v - d1) * 254.0f), -127.f), 127.f);
        q1[(size_t)o * 2048 + kk] = (int8_t)(int)d1;
        q2[(size_t)o * 2048 + kk] = (int8_t)(int)d2;
    }
    if (tid == 0) ws[o] = bm;
}

// ---------------- prep / glue kernels ----------------
__global__ void embed_split(const int* __restrict__ drug, const float* __restrict__ emb,
                            bf16* __restrict__ xh, bf16* __restrict__ xl) {
    int idx = blockIdx.x * blockDim.x + threadIdx.x;
    const int total = BATCH * LD * (DIM / 4);
    if (idx >= total) return;
    int d4 = idx & 31;
    int bl = idx >> 5;
    int tok = drug[bl];
    float4 v = ((const float4*)emb)[(size_t)tok * 32 + d4];
    size_t pos = (size_t)bl * 128 + d4 * 4;
    *(uint2*)(xh + pos) = make_uint2(pack2(v.x, v.y), pack2(v.z, v.w));
    *(uint2*)(xl + pos) = make_uint2(pack2(bf16lo_res(v.x), bf16lo_res(v.y)),
                                     pack2(bf16lo_res(v.z), bf16lo_res(v.w)));
}

__global__ void reorder_w_split(const float* __restrict__ w, bf16* __restrict__ wh,
                                bf16* __restrict__ wl, int O, int Ci, int Kw) {
    int idx = blockIdx.x * blockDim.x + threadIdx.x;
    int total = O * Ci * Kw;
    if (idx >= total) return;
    int o = idx / (Ci * Kw);
    int rr = idx - o * (Ci * Kw);
    int i = rr / Kw;
    int k = rr - i * Kw;
    size_t t = (size_t)o * Ci * Kw + k * Ci + i;
    split1(w[idx], wh[t], wl[t]);
}

__global__ void midtap_split(const float* __restrict__ w, bf16* __restrict__ wh,
                             bf16* __restrict__ wl, int total) {
    int idx = blockIdx.x * blockDim.x + threadIdx.x;
    if (idx >= total) return;
    split1(w[idx * 3 + 1], wh[idx], wl[idx]);
}

__global__ void midtap_f32(const float* __restrict__ w, float* __restrict__ wr, int total) {
    int idx = blockIdx.x * blockDim.x + threadIdx.x;
    if (idx >= total) return;
    wr[idx] = w[idx * 3 + 1];
}

__global__ void split_plain(const float* __restrict__ w, bf16* __restrict__ wh,
                            bf16* __restrict__ wl, int total) {
    int idx = blockIdx.x * blockDim.x + threadIdx.x;
    if (idx >= total) return;
    split1(w[idx], wh[idx], wl[idx]);
}

__global__ void feat1_k(const float* __restrict__ feat, const float* __restrict__ wm,
                        const float* __restrict__ bias,
                        bf16* __restrict__ oh, bf16* __restrict__ ol) {
    int idx = blockIdx.x * blockDim.x + threadIdx.x;
    if (idx >= BATCH * 128) return;
    int b = idx >> 7, o = idx & 127;
    float s = bias[o];
#pragma unroll
    for (int i = 0; i < 7; i++) s = fmaf(feat[b * 7 + i], wm[o * 7 + i], s);
    s = fmaxf(s, 0.f);
    split1(s, oh[idx], ol[idx]);
}

__global__ void reduce_k(const bf16* __restrict__ dch, const bf16* __restrict__ dcl,
                         const float* __restrict__ Am,
                         const bf16* __restrict__ fnnh, const bf16* __restrict__ fnnl,
                         bf16* __restrict__ ph, bf16* __restrict__ pl) {
    int b = blockIdx.x;
    int c = threadIdx.x;
    const size_t base = (size_t)b * L3O * 512 + c;
    float mx = -1e30f, smv = 0.f;
#pragma unroll 5
    for (int l = 0; l < L3O; l++) {
        float a = Am[base + (size_t)l * 512];
        float d = __bfloat162float(dch[base + (size_t)l * 512])
                + __bfloat162float(dcl[base + (size_t)l * 512]);
        float sg = 1.f / (1.f + expf(-a));
        mx = fmaxf(mx, d * (0.5f + sg));
        smv += a;
    }
    float fsig = 1.f / (1.f + expf(-smv * (1.0f / L3O)));
    float vf = (__bfloat162float(fnnh[(size_t)b * 512 + c])
              + __bfloat162float(fnnl[(size_t)b * 512 + c])) * (0.5f + fsig);
    split1(mx, ph[(size_t)b * 1024 + c],       pl[(size_t)b * 1024 + c]);
    split1(vf, ph[(size_t)b * 1024 + 512 + c], pl[(size_t)b * 1024 + 512 + c]);
}

__global__ void final_k(const float* __restrict__ h3, const float* __restrict__ Wo,
                        const float* __restrict__ bo, float* __restrict__ out) {
    int b = blockIdx.x;
    int t = threadIdx.x;
    float s = 0.f;
#pragma unroll
    for (int c = t; c < 512; c += 128) s = fmaf(h3[(size_t)b * 512 + c], Wo[c], s);
#pragma unroll
    for (int o = 16; o > 0; o >>= 1) s += __shfl_down_sync(0xffffffffu, s, o);
    __shared__ float red[4];
    if ((t & 31) == 0) red[t >> 5] = s;
    __syncthreads();
    if (t == 0) out[b] = red[0] + red[1] + red[2] + red[3] + bo[0];
}

// ---------------- host launch ----------------
#define GADDR(p, sym) cudaGetSymbolAddress((void**)&p, sym)

extern "C" void kernel_launch(void* const* d_in, const int* in_sizes, int n_in,
                              void* d_out, int out_size) {
    const int*   drug    = (const int*)  d_in[0];
    const float* feature = (const float*)d_in[1];
    const float* emb     = (const float*)d_in[2];
    const float* dw1 = (const float*)d_in[3];  const float* db1 = (const float*)d_in[4];
    const float* dw2 = (const float*)d_in[5];  const float* db2 = (const float*)d_in[6];
    const float* dw3 = (const float*)d_in[7];  const float* db3 = (const float*)d_in[8];
    const float* fw1 = (const float*)d_in[9];  const float* fb1 = (const float*)d_in[10];
    const float* fw2 = (const float*)d_in[11]; const float* fb2 = (const float*)d_in[12];
    const float* fw3 = (const float*)d_in[13]; const float* fb3 = (const float*)d_in[14];
    const float* Wda = (const float*)d_in[15]; const float* bda = (const float*)d_in[16];
    const float* Wfa = (const float*)d_in[17]; const float* bfa = (const float*)d_in[18];
    const float* Watt= (const float*)d_in[19]; const float* batt= (const float*)d_in[20];
    const float* W1  = (const float*)d_in[21]; const float* b1  = (const float*)d_in[22];
    const float* W2  = (const float*)d_in[23]; const float* b2  = (const float*)d_in[24];
    const float* W3  = (const float*)d_in[25]; const float* b3  = (const float*)d_in[26];
    const float* Wo  = (const float*)d_in[27]; const float* bo  = (const float*)d_in[28];
    float* out = (float*)d_out;

    bf16 *xh,*xl,*h1h,*h1l,*h2h,*h2l,*dch,*dcl,*atth,*attl;
    bf16 *hf1h,*hf1l,*hf2h,*hf2l,*fnnh,*fnnl,*pairh,*pairl,*fh1h,*fh1l,*fh2h,*fh2l;
    bf16 *w1rh,*w1rl,*w2rh,*w2rl,*fwm2h,*fwm2l,*fwm3h,*fwm3l;
    bf16 *Wdah,*Wdal,*Wfah,*Wfal,*Watth,*Wattl,*W1h,*W1l,*W2h,*W2l,*W3h,*W3l;
    float *Amf,*fattf,*fh3f,*fwm1,*w3s;
    unsigned *h2mb;
    int8_t *h2q1,*h2q2,*w3q1,*w3q2;
    GADDR(xh, g_xh); GADDR(xl, g_xl);
    GADDR(h1h, g_h1h); GADDR(h1l, g_h1l);
    GADDR(h2h, g_h2h); GADDR(h2l, g_h2l);
    GADDR(dch, g_dch); GADDR(dcl, g_dcl);
    GADDR(atth, g_atth); GADDR(attl, g_attl);
    GADDR(hf1h, g_hf1h); GADDR(hf1l, g_hf1l);
    GADDR(hf2h, g_hf2h); GADDR(hf2l, g_hf2l);
    GADDR(fnnh, g_fnnh); GADDR(fnnl, g_fnnl);
    GADDR(pairh, g_pairh); GADDR(pairl, g_pairl);
    GADDR(fh1h, g_fh1h); GADDR(fh1l, g_fh1l);
    GADDR(fh2h, g_fh2h); GADDR(fh2l, g_fh2l);
    GADDR(w1rh, g_w1rh); GADDR(w1rl, g_w1rl);
    GADDR(w2rh, g_w2rh); GADDR(w2rl, g_w2rl);
    GADDR(fwm2h, g_fwm2h); GADDR(fwm2l, g_fwm2l);
    GADDR(fwm3h, g_fwm3h); GADDR(fwm3l, g_fwm3l);
    GADDR(Wdah, g_Wdah); GADDR(Wdal, g_Wdal);
    GADDR(Wfah, g_Wfah); GADDR(Wfal, g_Wfal);
    GADDR(Watth, g_Watth); GADDR(Wattl, g_Wattl);
    GADDR(W1h, g_W1h); GADDR(W1l, g_W1l);
    GADDR(W2h, g_W2h); GADDR(W2l, g_W2l);
    GADDR(W3h, g_W3h); GADDR(W3l, g_W3l);
    GADDR(Amf, g_Amf); GADDR(fattf, g_fattf);
    GADDR(fh3f, g_fh3f); GADDR(fwm1, g_fwm1);
    GADDR(h2mb, g_h2maxbits);
    GADDR(h2q1, g_h2q1); GADDR(h2q2, g_h2q2);
    GADDR(w3q1, g_w3q1); GADDR(w3q2, g_w3q2); GADDR(w3s, g_w3s);

    cudaFuncSetAttribute(gemm2<0,0>, cudaFuncAttributeMaxDynamicSharedMemorySize, GSMEM);
    cudaFuncSetAttribute(gemm2<1,1>, cudaFuncAttributeMaxDynamicSharedMemorySize, GSMEM);
    cudaFuncSetAttribute(gemm2<3,1>, cudaFuncAttributeMaxDynamicSharedMemorySize, GSMEM);
    cudaFuncSetAttribute(gemm2<2,1>, cudaFuncAttributeMaxDynamicSharedMemorySize, GSMEM);
    cudaFuncSetAttribute(gemm2<2,0>, cudaFuncAttributeMaxDynamicSharedMemorySize, GSMEM);
    cudaFuncSetAttribute(gemm_i8_conv3, cudaFuncAttributeMaxDynamicSharedMemorySize, I8SMEM);

    // 0..4: prep (order keeps launch #5 = conv1 bf16 GEMM for ncu)
    reset_k<<<1, 32>>>(h2mb);                                                         // 0
    w3quant_k<<<512, 256>>>(dw3, w3q1, w3q2, w3s);                                    // 1
    embed_split<<<(BATCH * LD * 32 + 255) / 256, 256>>>(drug, emb, xh, xl);           // 2
    reorder_w_split<<<(128 * 128 * 4 + 255) / 256, 256>>>(dw1, w1rh, w1rl, 128, 128, 4); // 3
    reorder_w_split<<<(256 * 128 * 6 + 255) / 256, 256>>>(dw2, w2rh, w2rl, 256, 128, 6); // 4

    gemm2<1,1><<<dim3(1, (BATCH * L1O) / 256), 256, GSMEM>>>(xh, xl, w1rh, w1rl, db1,    // 5 (ncu)
        nullptr, nullptr, h1h, h1l, 128, 512, L1O, (long)LD * 128, 128L, 1);
    gemm2<1,1><<<dim3(2, (BATCH * L2O) / 256), 256, GSMEM>>>(h1h, h1l, w2rh, w2rl, db2,  // 6
        nullptr, nullptr, h2h, h2l, 256, 768, L2O, (long)L1O * 128, 128L, 1);

    // conv3: int8 path
    absmax_k<<<2048, 256>>>(h2h, H2ELEMS, h2mb);
    quant_k<<<(H2ELEMS + 255) / 256, 256>>>(h2h, h2l, h2mb, H2ELEMS, h2q1, h2q2);
    gemm_i8_conv3<<<dim3(4, (BATCH * L3O) / 128), 256, I8SMEM>>>(
        h2q1, h2q2, w3q1, w3q2, w3s, h2mb, db3, dch, dcl);

    // feature branch
    midtap_f32  <<<(128 * 7 + 255) / 256, 256>>>(fw1, fwm1, 128 * 7);
    midtap_split<<<(256 * 128 + 255) / 256, 256>>>(fw2, fwm2h, fwm2l, 256 * 128);
    midtap_split<<<(512 * 256 + 255) / 256, 256>>>(fw3, fwm3h, fwm3l, 512 * 256);
    split_plain<<<(512 * 512 + 255) / 256, 256>>>(Wda, Wdah, Wdal, 512 * 512);
    split_plain<<<(512 * 512 + 255) / 256, 256>>>(Wfa, Wfah, Wfal, 512 * 512);
    split_plain<<<(512 * 512 + 255) / 256, 256>>>(Watt, Watth, Wattl, 512 * 512);

    feat1_k<<<(BATCH * 128) / 256, 256>>>(feature, fwm1, fb1, hf1h, hf1l);
    gemm2<1,1><<<dim3(2, BATCH / 256), 256, GSMEM>>>(hf1h, hf1l, fwm2h, fwm2l, fb2,
        nullptr, nullptr, hf2h, hf2l, 256, 128, BATCH, 0L, 128L, 1);
    gemm2<1,1><<<dim3(4, BATCH / 256), 256, GSMEM>>>(hf2h, hf2l, fwm3h, fwm3l, fb3,
        nullptr, nullptr, fnnh, fnnl, 512, 256, BATCH, 0L, 256L, 1);
    gemm2<0,0><<<dim3(4, BATCH / 256), 256, GSMEM>>>(fnnh, fnnl, Wfah, Wfal, bfa,
        nullptr, fattf, nullptr, nullptr, 512, 512, BATCH, 0L, 512L, 1);

    // s = relu(dc @ Wda^T + bda + fatt[b]) fused
    gemm2<3,1><<<dim3(4, (BATCH * L3O) / 256), 256, GSMEM>>>(dch, dcl, Wdah, Wdal, bda,
        fattf, nullptr, atth, attl, 512, 512, BATCH * L3O, 0L, 512L, L3O);

    // A = s @ Watt^T + batt
    gemm2<0,0><<<dim3(4, (BATCH * L3O) / 256), 256, GSMEM>>>(atth, attl, Watth, Wattl, batt,
        nullptr, Amf, nullptr, nullptr, 512, 512, BATCH * L3O, 0L, 512L, 1);

    reduce_k<<<BATCH, 512>>>(dch, dcl, Amf, fnnh, fnnl, pairh, pairl);

    // FC head
    split_plain<<<(1024 * 1024 + 255) / 256, 256>>>(W1, W1h, W1l, 1024 * 1024);
    split_plain<<<(1024 * 1024 + 255) / 256, 256>>>(W2, W2h, W2l, 1024 * 1024);
    split_plain<<<(512 * 1024 + 255) / 256, 256>>>(W3, W3h, W3l, 512 * 1024);

    gemm2<2,1><<<dim3(8, BATCH / 256), 256, GSMEM>>>(pairh, pairl, W1h, W1l, b1,
        nullptr, nullptr, fh1h, fh1l, 1024, 1024, BATCH, 0L, 1024L, 1);
    gemm2<2,1><<<dim3(8, BATCH / 256), 256, GSMEM>>>(fh1h, fh1l, W2h, W2l, b2,
        nullptr, nullptr, fh2h, fh2l, 1024, 1024, BATCH, 0L, 1024L, 1);
    gemm2<2,0><<<dim3(4, BATCH / 256), 256, GSMEM>>>(fh2h, fh2l, W3h, W3l, b3,
        nullptr, fh3f, nullptr, nullptr, 512, 1024, BATCH, 0L, 1024L, 1);

    final_k<<<BATCH, 128>>>(fh3f, Wo, bo, out);
}

// round 7
// speedup vs baseline: 1.5392x; 1.5392x over previous
#include <cuda_runtime.h>
#include <cuda_bf16.h>
#include <cuda_fp16.h>
#include <math.h>
#include <stdint.h>

// ---------------- problem constants ----------------
#define BATCH 2048
#define LD    100
#define DIM   128
#define L1O   97
#define L2O   92
#define L3O   85

typedef __nv_bfloat16 bf16;

// ---------------- scratch (device globals; allocation-free) ----------------
__device__ bf16 g_xh [BATCH * LD  * DIM];   __device__ bf16 g_xl [BATCH * LD  * DIM];
__device__ bf16 g_h1h[BATCH * L1O * 128];   __device__ bf16 g_h1l[BATCH * L1O * 128];
__device__ bf16 g_h2h[BATCH * L2O * 256];   __device__ bf16 g_h2l[BATCH * L2O * 256];
__device__ bf16 g_dch[BATCH * L3O * 512];   __device__ bf16 g_dcl[BATCH * L3O * 512];
__device__ bf16 g_atth[BATCH * L3O * 512];  __device__ bf16 g_attl[BATCH * L3O * 512];
__device__ bf16 g_hf1h[BATCH * 128];        __device__ bf16 g_hf1l[BATCH * 128];
__device__ bf16 g_hf2h[BATCH * 256];        __device__ bf16 g_hf2l[BATCH * 256];
__device__ bf16 g_fnnh[BATCH * 512];        __device__ bf16 g_fnnl[BATCH * 512];
__device__ bf16 g_pairh[BATCH * 1024];      __device__ bf16 g_pairl[BATCH * 1024];
__device__ bf16 g_fh1h[BATCH * 1024];       __device__ bf16 g_fh1l[BATCH * 1024];
__device__ bf16 g_fh2h[BATCH * 1024];       __device__ bf16 g_fh2l[BATCH * 1024];
__device__ __half g_Amh[BATCH * L3O * 512];
__device__ __half g_fatth[BATCH * 512];
__device__ __half g_fh3h[BATCH * 512];
__device__ float g_fwm1[128 * 7];
__device__ bf16 g_w1rh[128 * 512];   __device__ bf16 g_w1rl[128 * 512];
__device__ bf16 g_w2rh[256 * 768];   __device__ bf16 g_w2rl[256 * 768];
__device__ bf16 g_w3rh[512 * 2048];  __device__ bf16 g_w3rl[512 * 2048];
__device__ bf16 g_fwm2h[256 * 128];  __device__ bf16 g_fwm2l[256 * 128];
__device__ bf16 g_fwm3h[512 * 256];  __device__ bf16 g_fwm3l[512 * 256];
__device__ bf16 g_Wdah[512 * 512];   __device__ bf16 g_Wdal[512 * 512];
__device__ bf16 g_Wfah[512 * 512];   __device__ bf16 g_Wfal[512 * 512];
__device__ bf16 g_Watth[512 * 512];  __device__ bf16 g_Wattl[512 * 512];
__device__ bf16 g_W1h[1024 * 1024];  __device__ bf16 g_W1l[1024 * 1024];
__device__ bf16 g_W2h[1024 * 1024];  __device__ bf16 g_W2l[1024 * 1024];
__device__ bf16 g_W3h[512 * 1024];   __device__ bf16 g_W3l[512 * 1024];

// ---------------- helpers ----------------
__device__ __forceinline__ uint32_t smem_u32(const void* p) {
    uint32_t a;
    asm("{ .reg .u64 t; cvta.to.shared.u64 t, %1; cvt.u32.u64 %0, t; }"
        : "=r"(a) : "l"(p));
    return a;
}
__device__ __forceinline__ void ldm4(uint32_t* r, uint32_t saddr) {
    asm volatile("ldmatrix.sync.aligned.m8n8.x4.shared.b16 {%0,%1,%2,%3}, [%4];"
        : "=r"(r[0]), "=r"(r[1]), "=r"(r[2]), "=r"(r[3]) : "r"(saddr));
}
__device__ __forceinline__ void mma16816(float* d, const uint32_t* a,
                                         uint32_t b0, uint32_t b1) {
    asm volatile(
        "mma.sync.aligned.m16n8k16.row.col.f32.bf16.bf16.f32 "
        "{%0,%1,%2,%3}, {%4,%5,%6,%7}, {%8,%9}, {%0,%1,%2,%3};"
        : "+f"(d[0]), "+f"(d[1]), "+f"(d[2]), "+f"(d[3])
        : "r"(a[0]), "r"(a[1]), "r"(a[2]), "r"(a[3]), "r"(b0), "r"(b1));
}
#define CPA16(dst, src) \
    asm volatile("cp.async.cg.shared.global [%0], [%1], 16;" :: "r"(dst), "l"(src) : "memory")
#define CPCOMMIT() asm volatile("cp.async.commit_group;" ::: "memory")
template <int NW> __device__ __forceinline__ void cpwait() {
    asm volatile("cp.async.wait_group %0;" :: "n"(NW) : "memory");
}
__device__ __forceinline__ uint32_t pack2(float x, float y) {
    bf16 a = __float2bfloat16(x), b = __float2bfloat16(y);
    return (uint32_t)__bfloat16_as_ushort(a) | ((uint32_t)__bfloat16_as_ushort(b) << 16);
}
__device__ __forceinline__ float bf16lo_res(float x) {
    return x - __bfloat162float(__float2bfloat16(x));
}
__device__ __forceinline__ void split1(float v, bf16& h, bf16& l) {
    h = __float2bfloat16(v);
    l = __float2bfloat16(v - __bfloat162float(h));
}

// epilogue activation + store (shared by both GEMMs)
template <int ACT, int OM>
__device__ __forceinline__ void epi_store(float vx, float vy, long rowb, int n,
                                          __half* Cf, bf16* Ch, bf16* Cl) {
    if (ACT == 1 || ACT == 3) {
        vx = fmaxf(vx, 0.f); vy = fmaxf(vy, 0.f);
    } else if (ACT == 2) {
        vx = vx > 0.f ? vx : 0.01f * vx;
        vy = vy > 0.f ? vy : 0.01f * vy;
    }
    if (OM == 0) {
        *(__half2*)(Cf + rowb + n) = __floats2half2_rn(vx, vy);
    } else {
        *(uint32_t*)(Ch + rowb + n) = pack2(vx, vy);
        *(uint32_t*)(Cl + rowb + n) = pack2(bf16lo_res(vx), bf16lo_res(vy));
    }
}

// ---------------- big GEMM: CTA 256x128, warp 64x64 (unchanged core from R5) ----------------
#define ROWB   80u
#define AREG   20480u
#define BREG   10240u
#define STG    61440u
#define GSMEM  (2 * 61440)

template <int ACT, int OM>  // ACT: 0 none,1 relu,2 leaky,3 relu(bias+extra); OM: 0 f16,1 hilo
__global__ __launch_bounds__(256, 1)
void gemm2(const bf16* __restrict__ Ah, const bf16* __restrict__ Al,
           const bf16* __restrict__ Wh, const bf16* __restrict__ Wl,
           const float* __restrict__ bias, const __half* __restrict__ extra,
           __half* __restrict__ Cf, bf16* __restrict__ Ch, bf16* __restrict__ Cl,
           int N, int K, int Lout, long sOuter, long sInner, int rowdiv) {
    extern __shared__ char sm[];
    const uint32_t smb = smem_u32(sm);
    const int tid = threadIdx.x;
    const int wid = tid >> 5, lane = tid & 31;
    const int m0 = blockIdx.y * 256, n0 = blockIdx.x * 128;
    const int wm = wid >> 1, wn = wid & 1;

    const int mrow = m0 + tid;
    const long aoff = (long)(mrow / Lout) * sOuter + (long)(mrow % Lout) * sInner;
    const bf16* aH = Ah + aoff;
    const bf16* aL = Al + aoff;
    const int brow = n0 + (tid >> 1);
    const bf16* bH = Wh + (long)brow * K;
    const bf16* bL = Wl + (long)brow * K;
    const int bseg = (tid & 1) * 2;

    const uint32_t aDst = smb + (uint32_t)tid * ROWB;
    const uint32_t bDst = smb + 2u * AREG + (uint32_t)(tid >> 1) * ROWB + (uint32_t)bseg * 16u;

    const int laneR = lane & 15;
    const uint32_t laneC = (uint32_t)(lane >> 4) * 16u;
    const uint32_t aBase = smb + (uint32_t)(wm * 64 + laneR) * ROWB + laneC;
    const uint32_t bBase = smb + 2u * AREG + (uint32_t)(wn * 64 + laneR) * ROWB + laneC;

    float acc[4][8][4];
#pragma unroll
    for (int i = 0; i < 4; i++)
#pragma unroll
        for (int j = 0; j < 8; j++)
#pragma unroll
            for (int k = 0; k < 4; k++) acc[i][j][k] = 0.f;

    const int T = K / 32;
    {
#pragma unroll
        for (int s = 0; s < 4; s++) CPA16(aDst + s * 16u, aH + s * 8);
#pragma unroll
        for (int s = 0; s < 4; s++) CPA16(aDst + AREG + s * 16u, aL + s * 8);
#pragma unroll
        for (int s = 0; s < 2; s++) CPA16(bDst + s * 16u, bH + (bseg + s) * 8);
#pragma unroll
        for (int s = 0; s < 2; s++) CPA16(bDst + BREG + s * 16u, bL + (bseg + s) * 8);
        CPCOMMIT();
    }

    for (int t = 0; t < T; ++t) {
        if (t + 1 < T) {
            const int k0 = (t + 1) * 32;
            const uint32_t sb = (uint32_t)((t + 1) & 1) * STG;
#pragma unroll
            for (int s = 0; s < 4; s++) CPA16(aDst + sb + s * 16u, aH + k0 + s * 8);
#pragma unroll
            for (int s = 0; s < 4; s++) CPA16(aDst + sb + AREG + s * 16u, aL + k0 + s * 8);
#pragma unroll
            for (int s = 0; s < 2; s++) CPA16(bDst + sb + s * 16u, bH + k0 + (bseg + s) * 8);
#pragma unroll
            for (int s = 0; s < 2; s++) CPA16(bDst + sb + BREG + s * 16u, bL + k0 + (bseg + s) * 8);
            CPCOMMIT();
            cpwait<1>();
        } else {
            cpwait<0>();
        }
        __syncthreads();

        const uint32_t soff = (uint32_t)(t & 1) * STG;
#pragma unroll
        for (int j = 0; j < 2; j++) {
            const uint32_t ja = soff + (uint32_t)j * 32u;
            uint32_t ah[4][4], al[4][4], bh[4][4], bl[4][4];
#pragma unroll
            for (int mt = 0; mt < 4; mt++) {
                ldm4(ah[mt], aBase + ja + (uint32_t)mt * (16u * ROWB));
                ldm4(al[mt], aBase + ja + (uint32_t)mt * (16u * ROWB) + AREG);
            }
#pragma unroll
            for (int nt = 0; nt < 4; nt++) {
                ldm4(bh[nt], bBase + ja + (uint32_t)nt * (16u * ROWB));
                ldm4(bl[nt], bBase + ja + (uint32_t)nt * (16u * ROWB) + BREG);
            }
#pragma unroll
            for (int nt = 0; nt < 4; nt++)
#pragma unroll
                for (int mt = 0; mt < 4; mt++) {
                    mma16816(acc[mt][2 * nt],     ah[mt], bh[nt][0], bh[nt][2]);
                    mma16816(acc[mt][2 * nt + 1], ah[mt], bh[nt][1], bh[nt][3]);
                }
#pragma unroll
            for (int nt = 0; nt < 4; nt++)
#pragma unroll
                for (int mt = 0; mt < 4; mt++) {
                    mma16816(acc[mt][2 * nt],     al[mt], bh[nt][0], bh[nt][2]);
                    mma16816(acc[mt][2 * nt + 1], al[mt], bh[nt][1], bh[nt][3]);
                }
#pragma unroll
            for (int nt = 0; nt < 4; nt++)
#pragma unroll
                for (int mt = 0; mt < 4; mt++) {
                    mma16816(acc[mt][2 * nt],     ah[mt], bl[nt][0], bl[nt][2]);
                    mma16816(acc[mt][2 * nt + 1], ah[mt], bl[nt][1], bl[nt][3]);
                }
        }
        __syncthreads();
    }

    const int lr2 = lane >> 2;
    const int lc2 = (lane & 3) * 2;
#pragma unroll
    for (int mt = 0; mt < 4; mt++) {
#pragma unroll
        for (int h = 0; h < 2; h++) {
            const long m = (long)m0 + wm * 64 + mt * 16 + h * 8 + lr2;
            const long rowb = m * (long)N;
            const __half* erow = (ACT == 3) ? (extra + (long)(m / rowdiv) * N) : nullptr;
#pragma unroll
            for (int nt2 = 0; nt2 < 8; nt2++) {
                const int n = n0 + wn * 64 + nt2 * 8 + lc2;
                float vx = acc[mt][nt2][2 * h]     + bias[n];
                float vy = acc[mt][nt2][2 * h + 1] + bias[n + 1];
                if (ACT == 3) {
                    float2 e = __half22float2(*(const __half2*)(erow + n));
                    vx += e.x; vy += e.y;
                }
                epi_store<ACT, OM>(vx, vy, rowb, n, Cf, Ch, Cl);
            }
        }
    }
}

// ---------------- small GEMM: CTA 128x128, warp 32x64 (for small-M layers) ----------------
#define SROWB   80u
#define SPLANE  10240u
#define SSTG    40960u
#define SSMEM   (2 * 40960)

template <int ACT, int OM>
__global__ __launch_bounds__(256, 1)
void gemmS(const bf16* __restrict__ Ah, const bf16* __restrict__ Al,
           const bf16* __restrict__ Wh, const bf16* __restrict__ Wl,
           const float* __restrict__ bias, const __half* __restrict__ extra,
           __half* __restrict__ Cf, bf16* __restrict__ Ch, bf16* __restrict__ Cl,
           int N, int K, int Lout, long sOuter, long sInner, int rowdiv) {
    extern __shared__ char sm[];
    const uint32_t smb = smem_u32(sm);
    const int tid = threadIdx.x;
    const int wid = tid >> 5, lane = tid & 31;
    const int m0 = blockIdx.y * 128, n0 = blockIdx.x * 128;
    const int wm = wid >> 1, wn = wid & 1;

    // loaders: 2 threads per row (row = tid>>1, 16-bf16 half = tid&1)
    const int lrow = tid >> 1;
    const int lc   = (tid & 1) * 16;
    const int mrow = m0 + lrow;
    const long aoff = (long)(mrow / Lout) * sOuter + (long)(mrow % Lout) * sInner + lc;
    const bf16* aH = Ah + aoff;
    const bf16* aL = Al + aoff;
    const bf16* bH = Wh + (long)(n0 + lrow) * K + lc;
    const bf16* bL = Wl + (long)(n0 + lrow) * K + lc;
    const uint32_t rowDst = smb + (uint32_t)lrow * SROWB + (uint32_t)(tid & 1) * 32u;

    const int laneR = lane & 15;
    const uint32_t laneC = (uint32_t)(lane >> 4) * 16u;
    const uint32_t aBase = smb + (uint32_t)(wm * 32 + laneR) * SROWB + laneC;
    const uint32_t bBase = smb + 2u * SPLANE + (uint32_t)(wn * 64 + laneR) * SROWB + laneC;

    float acc[2][8][4];
#pragma unroll
    for (int i = 0; i < 2; i++)
#pragma unroll
        for (int j = 0; j < 8; j++)
#pragma unroll
            for (int k = 0; k < 4; k++) acc[i][j][k] = 0.f;

    const int T = K / 32;
    {
#pragma unroll
        for (int s = 0; s < 2; s++) {
            CPA16(rowDst + s * 16u,              aH + s * 8);
            CPA16(rowDst + SPLANE + s * 16u,     aL + s * 8);
            CPA16(rowDst + 2u * SPLANE + s * 16u, bH + s * 8);
            CPA16(rowDst + 3u * SPLANE + s * 16u, bL + s * 8);
        }
        CPCOMMIT();
    }

    for (int t = 0; t < T; ++t) {
        if (t + 1 < T) {
            const int k0 = (t + 1) * 32;
            const uint32_t sb = (uint32_t)((t + 1) & 1) * SSTG;
#pragma unroll
            for (int s = 0; s < 2; s++) {
                CPA16(rowDst + sb + s * 16u,               aH + k0 + s * 8);
                CPA16(rowDst + sb + SPLANE + s * 16u,      aL + k0 + s * 8);
                CPA16(rowDst + sb + 2u * SPLANE + s * 16u, bH + k0 + s * 8);
                CPA16(rowDst + sb + 3u * SPLANE + s * 16u, bL + k0 + s * 8);
            }
            CPCOMMIT();
            cpwait<1>();
        } else {
            cpwait<0>();
        }
        __syncthreads();

        const uint32_t soff = (uint32_t)(t & 1) * SSTG;
#pragma unroll
        for (int j = 0; j < 2; j++) {
            const uint32_t ja = soff + (uint32_t)j * 32u;
            uint32_t ah[2][4], al[2][4], bh[4][4], bl[4][4];
#pragma unroll
            for (int mt = 0; mt < 2; mt++) {
                ldm4(ah[mt], aBase + ja + (uint32_t)mt * (16u * SROWB));
                ldm4(al[mt], aBase + ja + (uint32_t)mt * (16u * SROWB) + SPLANE);
            }
#pragma unroll
            for (int nt = 0; nt < 4; nt++) {
                ldm4(bh[nt], bBase + ja + (uint32_t)nt * (16u * SROWB));
                ldm4(bl[nt], bBase + ja + (uint32_t)nt * (16u * SROWB) + SPLANE);
            }
#pragma unroll
            for (int nt = 0; nt < 4; nt++)
#pragma unroll
                for (int mt = 0; mt < 2; mt++) {
                    mma16816(acc[mt][2 * nt],     ah[mt], bh[nt][0], bh[nt][2]);
                    mma16816(acc[mt][2 * nt + 1], ah[mt], bh[nt][1], bh[nt][3]);
                }
#pragma unroll
            for (int nt = 0; nt < 4; nt++)
#pragma unroll
                for (int mt = 0; mt < 2; mt++) {
                    mma16816(acc[mt][2 * nt],     al[mt], bh[nt][0], bh[nt][2]);
                    mma16816(acc[mt][2 * nt + 1], al[mt], bh[nt][1], bh[nt][3]);
                }
#pragma unroll
            for (int nt = 0; nt < 4; nt++)
#pragma unroll
                for (int mt = 0; mt < 2; mt++) {
                    mma16816(acc[mt][2 * nt],     ah[mt], bl[nt][0], bl[nt][2]);
                    mma16816(acc[mt][2 * nt + 1], ah[mt], bl[nt][1], bl[nt][3]);
                }
        }
        __syncthreads();
    }

    const int lr2 = lane >> 2;
    const int lc2 = (lane & 3) * 2;
#pragma unroll
    for (int mt = 0; mt < 2; mt++) {
#pragma unroll
        for (int h = 0; h < 2; h++) {
            const long m = (long)m0 + wm * 32 + mt * 16 + h * 8 + lr2;
            const long rowb = m * (long)N;
            const __half* erow = (ACT == 3) ? (extra + (long)(m / rowdiv) * N) : nullptr;
#pragma unroll
            for (int nt2 = 0; nt2 < 8; nt2++) {
                const int n = n0 + wn * 64 + nt2 * 8 + lc2;
                float vx = acc[mt][nt2][2 * h]     + bias[n];
                float vy = acc[mt][nt2][2 * h + 1] + bias[n + 1];
                if (ACT == 3) {
                    float2 e = __half22float2(*(const __half2*)(erow + n));
                    vx += e.x; vy += e.y;
                }
                epi_store<ACT, OM>(vx, vy, rowb, n, Cf, Ch, Cl);
            }
        }
    }
}

// ---------------- prep / glue kernels ----------------
__global__ void embed_split(const int* __restrict__ drug, const float* __restrict__ emb,
                            bf16* __restrict__ xh, bf16* __restrict__ xl) {
    int idx = blockIdx.x * blockDim.x + threadIdx.x;
    const int total = BATCH * LD * (DIM / 4);
    if (idx >= total) return;
    int d4 = idx & 31;
    int bl = idx >> 5;
    int tok = drug[bl];
    float4 v = ((const float4*)emb)[(size_t)tok * 32 + d4];
    size_t pos = (size_t)bl * 128 + d4 * 4;
    *(uint2*)(xh + pos) = make_uint2(pack2(v.x, v.y), pack2(v.z, v.w));
    *(uint2*)(xl + pos) = make_uint2(pack2(bf16lo_res(v.x), bf16lo_res(v.y)),
                                     pack2(bf16lo_res(v.z), bf16lo_res(v.w)));
}

__global__ void reorder_w_split(const float* __restrict__ w, bf16* __restrict__ wh,
                                bf16* __restrict__ wl, int O, int Ci, int Kw) {
    int idx = blockIdx.x * blockDim.x + threadIdx.x;
    int total = O * Ci * Kw;
    if (idx >= total) return;
    int o = idx / (Ci * Kw);
    int rr = idx - o * (Ci * Kw);
    int i = rr / Kw;
    int k = rr - i * Kw;
    size_t t = (size_t)o * Ci * Kw + k * Ci + i;
    split1(w[idx], wh[t], wl[t]);
}

__global__ void midtap_split(const float* __restrict__ w, bf16* __restrict__ wh,
                             bf16* __restrict__ wl, int total) {
    int idx = blockIdx.x * blockDim.x + threadIdx.x;
    if (idx >= total) return;
    split1(w[idx * 3 + 1], wh[idx], wl[idx]);
}

__global__ void midtap_f32(const float* __restrict__ w, float* __restrict__ wr, int total) {
    int idx = blockIdx.x * blockDim.x + threadIdx.x;
    if (idx >= total) return;
    wr[idx] = w[idx * 3 + 1];
}

__global__ void split_plain(const float* __restrict__ w, bf16* __restrict__ wh,
                            bf16* __restrict__ wl, int total) {
    int idx = blockIdx.x * blockDim.x + threadIdx.x;
    if (idx >= total) return;
    split1(w[idx], wh[idx], wl[idx]);
}

__global__ void feat1_k(const float* __restrict__ feat, const float* __restrict__ wm,
                        const float* __restrict__ bias,
                        bf16* __restrict__ oh, bf16* __restrict__ ol) {
    int idx = blockIdx.x * blockDim.x + threadIdx.x;
    if (idx >= BATCH * 128) return;
    int b = idx >> 7, o = idx & 127;
    float s = bias[o];
#pragma unroll
    for (int i = 0; i < 7; i++) s = fmaf(feat[b * 7 + i], wm[o * 7 + i], s);
    s = fmaxf(s, 0.f);
    split1(s, oh[idx], ol[idx]);
}

__global__ void reduce_k(const bf16* __restrict__ dch, const bf16* __restrict__ dcl,
                         const __half* __restrict__ Am,
                         const bf16* __restrict__ fnnh, const bf16* __restrict__ fnnl,
                         bf16* __restrict__ ph, bf16* __restrict__ pl) {
    int b = blockIdx.x;
    int c = threadIdx.x;
    const size_t base = (size_t)b * L3O * 512 + c;
    float mx = -1e30f, smv = 0.f;
#pragma unroll 5
    for (int l = 0; l < L3O; l++) {
        float a = __half2float(Am[base + (size_t)l * 512]);
        float d = __bfloat162float(dch[base + (size_t)l * 512])
                + __bfloat162float(dcl[base + (size_t)l * 512]);
        float sg = 1.f / (1.f + expf(-a));
        mx = fmaxf(mx, d * (0.5f + sg));
        smv += a;
    }
    float fsig = 1.f / (1.f + expf(-smv * (1.0f / L3O)));
    float vf = (__bfloat162float(fnnh[(size_t)b * 512 + c])
              + __bfloat162float(fnnl[(size_t)b * 512 + c])) * (0.5f + fsig);
    split1(mx, ph[(size_t)b * 1024 + c],       pl[(size_t)b * 1024 + c]);
    split1(vf, ph[(size_t)b * 1024 + 512 + c], pl[(size_t)b * 1024 + 512 + c]);
}

__global__ void final_k(const __half* __restrict__ h3, const float* __restrict__ Wo,
                        const float* __restrict__ bo, float* __restrict__ out) {
    int b = blockIdx.x;
    int t = threadIdx.x;
    float s = 0.f;
#pragma unroll
    for (int c = t; c < 512; c += 128)
        s = fmaf(__half2float(h3[(size_t)b * 512 + c]), Wo[c], s);
#pragma unroll
    for (int o = 16; o > 0; o >>= 1) s += __shfl_down_sync(0xffffffffu, s, o);
    __shared__ float red[4];
    if ((t & 31) == 0) red[t >> 5] = s;
    __syncthreads();
    if (t == 0) out[b] = red[0] + red[1] + red[2] + red[3] + bo[0];
}

// ---------------- host launch ----------------
#define GADDR(p, sym) cudaGetSymbolAddress((void**)&p, sym)

extern "C" void kernel_launch(void* const* d_in, const int* in_sizes, int n_in,
                              void* d_out, int out_size) {
    const int*   drug    = (const int*)  d_in[0];
    const float* feature = (const float*)d_in[1];
    const float* emb     = (const float*)d_in[2];
    const float* dw1 = (const float*)d_in[3];  const float* db1 = (const float*)d_in[4];
    const float* dw2 = (const float*)d_in[5];  const float* db2 = (const float*)d_in[6];
    const float* dw3 = (const float*)d_in[7];  const float* db3 = (const float*)d_in[8];
    const float* fw1 = (const float*)d_in[9];  const float* fb1 = (const float*)d_in[10];
    const float* fw2 = (const float*)d_in[11]; const float* fb2 = (const float*)d_in[12];
    const float* fw3 = (const float*)d_in[13]; const float* fb3 = (const float*)d_in[14];
    const float* Wda = (const float*)d_in[15]; const float* bda = (const float*)d_in[16];
    const float* Wfa = (const float*)d_in[17]; const float* bfa = (const float*)d_in[18];
    const float* Watt= (const float*)d_in[19]; const float* batt= (const float*)d_in[20];
    const float* W1  = (const float*)d_in[21]; const float* b1  = (const float*)d_in[22];
    const float* W2  = (const float*)d_in[23]; const float* b2  = (const float*)d_in[24];
    const float* W3  = (const float*)d_in[25]; const float* b3  = (const float*)d_in[26];
    const float* Wo  = (const float*)d_in[27]; const float* bo  = (const float*)d_in[28];
    float* out = (float*)d_out;

    bf16 *xh,*xl,*h1h,*h1l,*h2h,*h2l,*dch,*dcl,*atth,*attl;
    bf16 *hf1h,*hf1l,*hf2h,*hf2l,*fnnh,*fnnl,*pairh,*pairl,*fh1h,*fh1l,*fh2h,*fh2l;
    bf16 *w1rh,*w1rl,*w2rh,*w2rl,*w3rh,*w3rl,*fwm2h,*fwm2l,*fwm3h,*fwm3l;
    bf16 *Wdah,*Wdal,*Wfah,*Wfal,*Watth,*Wattl,*W1h,*W1l,*W2h,*W2l,*W3h,*W3l;
    __half *Amh,*fatth,*fh3h;
    float *fwm1;
    GADDR(xh, g_xh); GADDR(xl, g_xl);
    GADDR(h1h, g_h1h); GADDR(h1l, g_h1l);
    GADDR(h2h, g_h2h); GADDR(h2l, g_h2l);
    GADDR(dch, g_dch); GADDR(dcl, g_dcl);
    GADDR(atth, g_atth); GADDR(attl, g_attl);
    GADDR(hf1h, g_hf1h); GADDR(hf1l, g_hf1l);
    GADDR(hf2h, g_hf2h); GADDR(hf2l, g_hf2l);
    GADDR(fnnh, g_fnnh); GADDR(fnnl, g_fnnl);
    GADDR(pairh, g_pairh); GADDR(pairl, g_pairl);
    GADDR(fh1h, g_fh1h); GADDR(fh1l, g_fh1l);
    GADDR(fh2h, g_fh2h); GADDR(fh2l, g_fh2l);
    GADDR(w1rh, g_w1rh); GADDR(w1rl, g_w1rl);
    GADDR(w2rh, g_w2rh); GADDR(w2rl, g_w2rl);
    GADDR(w3rh, g_w3rh); GADDR(w3rl, g_w3rl);
    GADDR(fwm2h, g_fwm2h); GADDR(fwm2l, g_fwm2l);
    GADDR(fwm3h, g_fwm3h); GADDR(fwm3l, g_fwm3l);
    GADDR(Wdah, g_Wdah); GADDR(Wdal, g_Wdal);
    GADDR(Wfah, g_Wfah); GADDR(Wfal, g_Wfal);
    GADDR(Watth, g_Watth); GADDR(Wattl, g_Wattl);
    GADDR(W1h, g_W1h); GADDR(W1l, g_W1l);
    GADDR(W2h, g_W2h); GADDR(W2l, g_W2l);
    GADDR(W3h, g_W3h); GADDR(W3l, g_W3l);
    GADDR(Amh, g_Amh); GADDR(fatth, g_fatth); GADDR(fh3h, g_fh3h);
    GADDR(fwm1, g_fwm1);

    cudaFuncSetAttribute(gemm2<0,0>, cudaFuncAttributeMaxDynamicSharedMemorySize, GSMEM);
    cudaFuncSetAttribute(gemm2<1,1>, cudaFuncAttributeMaxDynamicSharedMemorySize, GSMEM);
    cudaFuncSetAttribute(gemm2<3,1>, cudaFuncAttributeMaxDynamicSharedMemorySize, GSMEM);
    cudaFuncSetAttribute(gemmS<0,0>, cudaFuncAttributeMaxDynamicSharedMemorySize, SSMEM);
    cudaFuncSetAttribute(gemmS<1,1>, cudaFuncAttributeMaxDynamicSharedMemorySize, SSMEM);
    cudaFuncSetAttribute(gemmS<2,1>, cudaFuncAttributeMaxDynamicSharedMemorySize, SSMEM);
    cudaFuncSetAttribute(gemmS<2,0>, cudaFuncAttributeMaxDynamicSharedMemorySize, SSMEM);

    // prep (launch index 5 = conv1 GEMM for ncu -s 5)
    embed_split<<<(BATCH * LD * 32 + 255) / 256, 256>>>(drug, emb, xh, xl);               // 0
    reorder_w_split<<<(128 * 128 * 4 + 255) / 256, 256>>>(dw1, w1rh, w1rl, 128, 128, 4);  // 1
    reorder_w_split<<<(256 * 128 * 6 + 255) / 256, 256>>>(dw2, w2rh, w2rl, 256, 128, 6);  // 2
    reorder_w_split<<<(512 * 256 * 8 + 255) / 256, 256>>>(dw3, w3rh, w3rl, 512, 256, 8);  // 3
    midtap_f32<<<(128 * 7 + 255) / 256, 256>>>(fw1, fwm1, 128 * 7);                       // 4

    // drug conv stack
    gemmS<1,1><<<dim3(1, (BATCH * L1O) / 128), 256, SSMEM>>>(xh, xl, w1rh, w1rl, db1,     // 5 (ncu)
        nullptr, nullptr, h1h, h1l, 128, 512, L1O, (long)LD * 128, 128L, 1);
    gemm2<1,1><<<dim3(2, (BATCH * L2O) / 256), 256, GSMEM>>>(h1h, h1l, w2rh, w2rl, db2,
        nullptr, nullptr, h2h, h2l, 256, 768, L2O, (long)L1O * 128, 128L, 1);
    gemm2<1,1><<<dim3(4, (BATCH * L3O) / 256), 256, GSMEM>>>(h2h, h2l, w3rh, w3rl, db3,
        nullptr, nullptr, dch, dcl, 512, 2048, L3O, (long)L2O * 256, 256L, 1);

    // feature branch
    midtap_split<<<(256 * 128 + 255) / 256, 256>>>(fw2, fwm2h, fwm2l, 256 * 128);
    midtap_split<<<(512 * 256 + 255) / 256, 256>>>(fw3, fwm3h, fwm3l, 512 * 256);
    split_plain<<<(512 * 512 + 255) / 256, 256>>>(Wda, Wdah, Wdal, 512 * 512);
    split_plain<<<(512 * 512 + 255) / 256, 256>>>(Wfa, Wfah, Wfal, 512 * 512);
    split_plain<<<(512 * 512 + 255) / 256, 256>>>(Watt, Watth, Wattl, 512 * 512);

    feat1_k<<<(BATCH * 128) / 256, 256>>>(feature, fwm1, fb1, hf1h, hf1l);
    gemmS<1,1><<<dim3(2, BATCH / 128), 256, SSMEM>>>(hf1h, hf1l, fwm2h, fwm2l, fb2,
        nullptr, nullptr, hf2h, hf2l, 256, 128, BATCH, 0L, 128L, 1);
    gemmS<1,1><<<dim3(4, BATCH / 128), 256, SSMEM>>>(hf2h, hf2l, fwm3h, fwm3l, fb3,
        nullptr, nullptr, fnnh, fnnl, 512, 256, BATCH, 0L, 256L, 1);
    gemmS<0,0><<<dim3(4, BATCH / 128), 256, SSMEM>>>(fnnh, fnnl, Wfah, Wfal, bfa,
        nullptr, fatth, nullptr, nullptr, 512, 512, BATCH, 0L, 512L, 1);

    // s = relu(dc @ Wda^T + bda + fatt[b]) fused
    gemm2<3,1><<<dim3(4, (BATCH * L3O) / 256), 256, GSMEM>>>(dch, dcl, Wdah, Wdal, bda,
        fatth, nullptr, atth, attl, 512, 512, BATCH * L3O, 0L, 512L, L3O);

    // A = s @ Watt^T + batt (fp16 out)
    gemm2<0,0><<<dim3(4, (BATCH * L3O) / 256), 256, GSMEM>>>(atth, attl, Watth, Wattl, batt,
        nullptr, Amh, nullptr, nullptr, 512, 512, BATCH * L3O, 0L, 512L, 1);

    reduce_k<<<BATCH, 512>>>(dch, dcl, Amh, fnnh, fnnl, pairh, pairl);

    // FC head
    split_plain<<<(1024 * 1024 + 255) / 256, 256>>>(W1, W1h, W1l, 1024 * 1024);
    split_plain<<<(1024 * 1024 + 255) / 256, 256>>>(W2, W2h, W2l, 1024 * 1024);
    split_plain<<<(512 * 1024 + 255) / 256, 256>>>(W3, W3h, W3l, 512 * 1024);

    gemmS<2,1><<<dim3(8, BATCH / 128), 256, SSMEM>>>(pairh, pairl, W1h, W1l, b1,
        nullptr, nullptr, fh1h, fh1l, 1024, 1024, BATCH, 0L, 1024L, 1);
    gemmS<2,1><<<dim3(8, BATCH / 128), 256, SSMEM>>>(fh1h, fh1l, W2h, W2l, b2,
        nullptr, nullptr, fh2h, fh2l, 1024, 1024, BATCH, 0L, 1024L, 1);
    gemmS<2,0><<<dim3(4, BATCH / 128), 256, SSMEM>>>(fh2h, fh2l, W3h, W3l, b3,
        nullptr, fh3h, nullptr, nullptr, 512, 1024, BATCH, 0L, 1024L, 1);

    final_k<<<BATCH, 128>>>(fh3h, Wo, bo, out);
}

// round 8
// speedup vs baseline: 3.5068x; 2.2784x over previous
#include <cuda_runtime.h>
#include <cuda_fp16.h>
#include <math.h>
#include <stdint.h>

// ---------------- problem constants ----------------
#define BATCH 2048
#define LD    100
#define DIM   128
#define L1O   97
#define L2O   92
#define L3O   85

// ---------------- scratch (device globals; allocation-free) ----------------
__device__ __half g_x  [BATCH * LD  * DIM];
__device__ __half g_h1 [BATCH * L1O * 128];
__device__ __half g_h2 [BATCH * L2O * 256];
__device__ __half g_dc [BATCH * L3O * 512];
__device__ __half g_att[BATCH * L3O * 512];
__device__ __half g_hf1[BATCH * 128];
__device__ __half g_hf2[BATCH * 256];
__device__ __half g_fnn[BATCH * 512];
__device__ __half g_pair[BATCH * 1024];
__device__ __half g_fh1[BATCH * 1024];
__device__ __half g_fh2[BATCH * 1024];
__device__ float  g_Am [BATCH * L3O * 512];
__device__ float  g_fatt[BATCH * 512];
__device__ float  g_fh3[BATCH * 512];
__device__ float  g_fwm1[128 * 7];
__device__ __half g_w1r[128 * 512];
__device__ __half g_w2r[256 * 768];
__device__ __half g_w3r[512 * 2048];
__device__ __half g_fwm2[256 * 128];
__device__ __half g_fwm3[512 * 256];
__device__ __half g_Wda[512 * 512];
__device__ __half g_Wfa[512 * 512];
__device__ __half g_Watt[512 * 512];
__device__ __half g_W1[1024 * 1024];
__device__ __half g_W2[1024 * 1024];
__device__ __half g_W3[512 * 1024];

// ---------------- helpers ----------------
__device__ __forceinline__ uint32_t smem_u32(const void* p) {
    uint32_t a;
    asm("{ .reg .u64 t; cvta.to.shared.u64 t, %1; cvt.u32.u64 %0, t; }"
        : "=r"(a) : "l"(p));
    return a;
}
__device__ __forceinline__ void ldm4(uint32_t* r, uint32_t saddr) {
    asm volatile("ldmatrix.sync.aligned.m8n8.x4.shared.b16 {%0,%1,%2,%3}, [%4];"
        : "=r"(r[0]), "=r"(r[1]), "=r"(r[2]), "=r"(r[3]) : "r"(saddr));
}
__device__ __forceinline__ void mma16816(float* d, const uint32_t* a,
                                         uint32_t b0, uint32_t b1) {
    asm volatile(
        "mma.sync.aligned.m16n8k16.row.col.f32.f16.f16.f32 "
        "{%0,%1,%2,%3}, {%4,%5,%6,%7}, {%8,%9}, {%0,%1,%2,%3};"
        : "+f"(d[0]), "+f"(d[1]), "+f"(d[2]), "+f"(d[3])
        : "r"(a[0]), "r"(a[1]), "r"(a[2]), "r"(a[3]), "r"(b0), "r"(b1));
}
#define CPA16(dst, src) \
    asm volatile("cp.async.cg.shared.global [%0], [%1], 16;" :: "r"(dst), "l"(src) : "memory")
#define CPCOMMIT() asm volatile("cp.async.commit_group;" ::: "memory")
template <int NW> __device__ __forceinline__ void cpwait() {
    asm volatile("cp.async.wait_group %0;" :: "n"(NW) : "memory");
}

// epilogue activation + store
template <int ACT, int OM>  // OM: 0 fp32, 1 fp16
__device__ __forceinline__ void epi_store(float vx, float vy, long rowb, int n,
                                          float* Cf, __half* Ch) {
    if (ACT == 1 || ACT == 3) {
        vx = fmaxf(vx, 0.f); vy = fmaxf(vy, 0.f);
    } else if (ACT == 2) {
        vx = vx > 0.f ? vx : 0.01f * vx;
        vy = vy > 0.f ? vy : 0.01f * vy;
    }
    if (OM == 0) *(float2*)(Cf + rowb + n) = make_float2(vx, vy);
    else         *(__half2*)(Ch + rowb + n) = __floats2half2_rn(vx, vy);
}

// ---------------- big GEMM: CTA 256x128, warp 64x64, single fp16 plane ----------------
#define ROWB   80u
#define APLN   20480u            // 256 rows * 80B
#define GSTG   30720u            // A + B (128*80)
#define GSMEM  (2 * 30720)

template <int ACT, int OM>  // ACT: 0 none,1 relu,2 leaky,3 relu(bias+extra)
__global__ __launch_bounds__(256, 1)
void gemm2(const __half* __restrict__ A, const __half* __restrict__ W,
           const float* __restrict__ bias, const float* __restrict__ extra,
           float* __restrict__ Cf, __half* __restrict__ Ch,
           int N, int K, int Lout, long sOuter, long sInner, int rowdiv) {
    extern __shared__ char sm[];
    const uint32_t smb = smem_u32(sm);
    const int tid = threadIdx.x;
    const int wid = tid >> 5, lane = tid & 31;
    const int m0 = blockIdx.y * 256, n0 = blockIdx.x * 128;
    const int wm = wid >> 1, wn = wid & 1;

    const int mrow = m0 + tid;
    const __half* aP = A + (long)(mrow / Lout) * sOuter + (long)(mrow % Lout) * sInner;
    const int bseg = (tid & 1) * 2;
    const __half* bP = W + (long)(n0 + (tid >> 1)) * K;

    const uint32_t aDst = smb + (uint32_t)tid * ROWB;
    const uint32_t bDst = smb + APLN + (uint32_t)(tid >> 1) * ROWB + (uint32_t)bseg * 16u;

    const int laneR = lane & 15;
    const uint32_t laneC = (uint32_t)(lane >> 4) * 16u;
    const uint32_t aBase = smb + (uint32_t)(wm * 64 + laneR) * ROWB + laneC;
    const uint32_t bBase = smb + APLN + (uint32_t)(wn * 64 + laneR) * ROWB + laneC;

    float acc[4][8][4];
#pragma unroll
    for (int i = 0; i < 4; i++)
#pragma unroll
        for (int j = 0; j < 8; j++)
#pragma unroll
            for (int k = 0; k < 4; k++) acc[i][j][k] = 0.f;

    const int T = K / 32;
    {
#pragma unroll
        for (int s = 0; s < 4; s++) CPA16(aDst + s * 16u, aP + s * 8);
#pragma unroll
        for (int s = 0; s < 2; s++) CPA16(bDst + s * 16u, bP + (bseg + s) * 8);
        CPCOMMIT();
    }

    for (int t = 0; t < T; ++t) {
        if (t + 1 < T) {
            const int k0 = (t + 1) * 32;
            const uint32_t sb = (uint32_t)((t + 1) & 1) * GSTG;
#pragma unroll
            for (int s = 0; s < 4; s++) CPA16(aDst + sb + s * 16u, aP + k0 + s * 8);
#pragma unroll
            for (int s = 0; s < 2; s++) CPA16(bDst + sb + s * 16u, bP + k0 + (bseg + s) * 8);
            CPCOMMIT();
            cpwait<1>();
        } else {
            cpwait<0>();
        }
        __syncthreads();

        const uint32_t soff = (uint32_t)(t & 1) * GSTG;
#pragma unroll
        for (int j = 0; j < 2; j++) {
            const uint32_t ja = soff + (uint32_t)j * 32u;
            uint32_t af[4][4], bf[4][4];
#pragma unroll
            for (int mt = 0; mt < 4; mt++)
                ldm4(af[mt], aBase + ja + (uint32_t)mt * (16u * ROWB));
#pragma unroll
            for (int nt = 0; nt < 4; nt++)
                ldm4(bf[nt], bBase + ja + (uint32_t)nt * (16u * ROWB));
#pragma unroll
            for (int nt = 0; nt < 4; nt++)
#pragma unroll
                for (int mt = 0; mt < 4; mt++) {
                    mma16816(acc[mt][2 * nt],     af[mt], bf[nt][0], bf[nt][2]);
                    mma16816(acc[mt][2 * nt + 1], af[mt], bf[nt][1], bf[nt][3]);
                }
        }
        __syncthreads();
    }

    const int lr2 = lane >> 2;
    const int lc2 = (lane & 3) * 2;
#pragma unroll
    for (int mt = 0; mt < 4; mt++) {
#pragma unroll
        for (int h = 0; h < 2; h++) {
            const long m = (long)m0 + wm * 64 + mt * 16 + h * 8 + lr2;
            const long rowb = m * (long)N;
            const float* erow = (ACT == 3) ? (extra + (long)(m / rowdiv) * N) : nullptr;
#pragma unroll
            for (int nt2 = 0; nt2 < 8; nt2++) {
                const int n = n0 + wn * 64 + nt2 * 8 + lc2;
                float vx = acc[mt][nt2][2 * h]     + bias[n];
                float vy = acc[mt][nt2][2 * h + 1] + bias[n + 1];
                if (ACT == 3) {
                    float2 e = *(const float2*)(erow + n);
                    vx += e.x; vy += e.y;
                }
                epi_store<ACT, OM>(vx, vy, rowb, n, Cf, Ch);
            }
        }
    }
}

// ---------------- small GEMM: CTA 128x128, warp 32x64 ----------------
#define SPLN   10240u
#define SSTG   20480u
#define SSMEM  (2 * 20480)

template <int ACT, int OM>
__global__ __launch_bounds__(256, 1)
void gemmS(const __half* __restrict__ A, const __half* __restrict__ W,
           const float* __restrict__ bias, const float* __restrict__ extra,
           float* __restrict__ Cf, __half* __restrict__ Ch,
           int N, int K, int Lout, long sOuter, long sInner, int rowdiv) {
    extern __shared__ char sm[];
    const uint32_t smb = smem_u32(sm);
    const int tid = threadIdx.x;
    const int wid = tid >> 5, lane = tid & 31;
    const int m0 = blockIdx.y * 128, n0 = blockIdx.x * 128;
    const int wm = wid >> 1, wn = wid & 1;

    const int lrow = tid >> 1;
    const int lc   = (tid & 1) * 16;
    const int mrow = m0 + lrow;
    const __half* aP = A + (long)(mrow / Lout) * sOuter + (long)(mrow % Lout) * sInner + lc;
    const __half* bP = W + (long)(n0 + lrow) * K + lc;
    const uint32_t rowDst = smb + (uint32_t)lrow * ROWB + (uint32_t)(tid & 1) * 32u;

    const int laneR = lane & 15;
    const uint32_t laneC = (uint32_t)(lane >> 4) * 16u;
    const uint32_t aBase = smb + (uint32_t)(wm * 32 + laneR) * ROWB + laneC;
    const uint32_t bBase = smb + SPLN + (uint32_t)(wn * 64 + laneR) * ROWB + laneC;

    float acc[2][8][4];
#pragma unroll
    for (int i = 0; i < 2; i++)
#pragma unroll
        for (int j = 0; j < 8; j++)
#pragma unroll
            for (int k = 0; k < 4; k++) acc[i][j][k] = 0.f;

    const int T = K / 32;
    {
#pragma unroll
        for (int s = 0; s < 2; s++) {
            CPA16(rowDst + s * 16u,        aP + s * 8);
            CPA16(rowDst + SPLN + s * 16u, bP + s * 8);
        }
        CPCOMMIT();
    }

    for (int t = 0; t < T; ++t) {
        if (t + 1 < T) {
            const int k0 = (t + 1) * 32;
            const uint32_t sb = (uint32_t)((t + 1) & 1) * SSTG;
#pragma unroll
            for (int s = 0; s < 2; s++) {
                CPA16(rowDst + sb + s * 16u,        aP + k0 + s * 8);
                CPA16(rowDst + sb + SPLN + s * 16u, bP + k0 + s * 8);
            }
            CPCOMMIT();
            cpwait<1>();
        } else {
            cpwait<0>();
        }
        __syncthreads();

        const uint32_t soff = (uint32_t)(t & 1) * SSTG;
#pragma unroll
        for (int j = 0; j < 2; j++) {
            const uint32_t ja = soff + (uint32_t)j * 32u;
            uint32_t af[2][4], bf[4][4];
#pragma unroll
            for (int mt = 0; mt < 2; mt++)
                ldm4(af[mt], aBase + ja + (uint32_t)mt * (16u * ROWB));
#pragma unroll
            for (int nt = 0; nt < 4; nt++)
                ldm4(bf[nt], bBase + ja + (uint32_t)nt * (16u * ROWB));
#pragma unroll
            for (int nt = 0; nt < 4; nt++)
#pragma unroll
                for (int mt = 0; mt < 2; mt++) {
                    mma16816(acc[mt][2 * nt],     af[mt], bf[nt][0], bf[nt][2]);
                    mma16816(acc[mt][2 * nt + 1], af[mt], bf[nt][1], bf[nt][3]);
                }
        }
        __syncthreads();
    }

    const int lr2 = lane >> 2;
    const int lc2 = (lane & 3) * 2;
#pragma unroll
    for (int mt = 0; mt < 2; mt++) {
#pragma unroll
        for (int h = 0; h < 2; h++) {
            const long m = (long)m0 + wm * 32 + mt * 16 + h * 8 + lr2;
            const long rowb = m * (long)N;
            const float* erow = (ACT == 3) ? (extra + (long)(m / rowdiv) * N) : nullptr;
#pragma unroll
            for (int nt2 = 0; nt2 < 8; nt2++) {
                const int n = n0 + wn * 64 + nt2 * 8 + lc2;
                float vx = acc[mt][nt2][2 * h]     + bias[n];
                float vy = acc[mt][nt2][2 * h + 1] + bias[n + 1];
                if (ACT == 3) {
                    float2 e = *(const float2*)(erow + n);
                    vx += e.x; vy += e.y;
                }
                epi_store<ACT, OM>(vx, vy, rowb, n, Cf, Ch);
            }
        }
    }
}

// ---------------- prep / glue kernels ----------------
__global__ void embed_h(const int* __restrict__ drug, const float* __restrict__ emb,
                        __half* __restrict__ x) {
    int idx = blockIdx.x * blockDim.x + threadIdx.x;
    const int total = BATCH * LD * (DIM / 4);
    if (idx >= total) return;
    int d4 = idx & 31;
    int bl = idx >> 5;
    int tok = drug[bl];
    float4 v = ((const float4*)emb)[(size_t)tok * 32 + d4];
    size_t pos = (size_t)bl * 128 + d4 * 4;
    __half2 h0 = __floats2half2_rn(v.x, v.y);
    __half2 h1 = __floats2half2_rn(v.z, v.w);
    *(__half2*)(x + pos)     = h0;
    *(__half2*)(x + pos + 2) = h1;
}

__global__ void reorder_w_h(const float* __restrict__ w, __half* __restrict__ wr,
                            int O, int Ci, int Kw) {
    int idx = blockIdx.x * blockDim.x + threadIdx.x;
    int total = O * Ci * Kw;
    if (idx >= total) return;
    int o = idx / (Ci * Kw);
    int rr = idx - o * (Ci * Kw);
    int i = rr / Kw;
    int k = rr - i * Kw;
    wr[(size_t)o * Ci * Kw + k * Ci + i] = __float2half_rn(w[idx]);
}

__global__ void midtap_h(const float* __restrict__ w, __half* __restrict__ wr, int total) {
    int idx = blockIdx.x * blockDim.x + threadIdx.x;
    if (idx >= total) return;
    wr[idx] = __float2half_rn(w[idx * 3 + 1]);
}

__global__ void midtap_f32(const float* __restrict__ w, float* __restrict__ wr, int total) {
    int idx = blockIdx.x * blockDim.x + threadIdx.x;
    if (idx >= total) return;
    wr[idx] = w[idx * 3 + 1];
}

__global__ void conv_h(const float* __restrict__ w, __half* __restrict__ wr, int total) {
    int idx = blockIdx.x * blockDim.x + threadIdx.x;
    if (idx >= total) return;
    wr[idx] = __float2half_rn(w[idx]);
}

__global__ void feat1_k(const float* __restrict__ feat, const float* __restrict__ wm,
                        const float* __restrict__ bias, __half* __restrict__ o1) {
    int idx = blockIdx.x * blockDim.x + threadIdx.x;
    if (idx >= BATCH * 128) return;
    int b = idx >> 7, o = idx & 127;
    float s = bias[o];
#pragma unroll
    for (int i = 0; i < 7; i++) s = fmaf(feat[b * 7 + i], wm[o * 7 + i], s);
    o1[idx] = __float2half_rn(fmaxf(s, 0.f));
}

__global__ void reduce_k(const __half* __restrict__ dc, const float* __restrict__ Am,
                         const __half* __restrict__ fnn,
                         __half* __restrict__ pair) {
    int b = blockIdx.x;
    int c = threadIdx.x;
    const size_t base = (size_t)b * L3O * 512 + c;
    float mx = -1e30f, smv = 0.f;
#pragma unroll 5
    for (int l = 0; l < L3O; l++) {
        float a = Am[base + (size_t)l * 512];
        float d = __half2float(dc[base + (size_t)l * 512]);
        float sg = 1.f / (1.f + expf(-a));
        mx = fmaxf(mx, d * (0.5f + sg));
        smv += a;
    }
    float fsig = 1.f / (1.f + expf(-smv * (1.0f / L3O)));
    float vf = __half2float(fnn[(size_t)b * 512 + c]) * (0.5f + fsig);
    pair[(size_t)b * 1024 + c]       = __float2half_rn(mx);
    pair[(size_t)b * 1024 + 512 + c] = __float2half_rn(vf);
}

__global__ void final_k(const float* __restrict__ h3, const float* __restrict__ Wo,
                        const float* __restrict__ bo, float* __restrict__ out) {
    int b = blockIdx.x;
    int t = threadIdx.x;
    float s = 0.f;
#pragma unroll
    for (int c = t; c < 512; c += 128) s = fmaf(h3[(size_t)b * 512 + c], Wo[c], s);
#pragma unroll
    for (int o = 16; o > 0; o >>= 1) s += __shfl_down_sync(0xffffffffu, s, o);
    __shared__ float red[4];
    if ((t & 31) == 0) red[t >> 5] = s;
    __syncthreads();
    if (t == 0) out[b] = red[0] + red[1] + red[2] + red[3] + bo[0];
}

// ---------------- host launch ----------------
#define GADDR(p, sym) cudaGetSymbolAddress((void**)&p, sym)

extern "C" void kernel_launch(void* const* d_in, const int* in_sizes, int n_in,
                              void* d_out, int out_size) {
    const int*   drug    = (const int*)  d_in[0];
    const float* feature = (const float*)d_in[1];
    const float* emb     = (const float*)d_in[2];
    const float* dw1 = (const float*)d_in[3];  const float* db1 = (const float*)d_in[4];
    const float* dw2 = (const float*)d_in[5];  const float* db2 = (const float*)d_in[6];
    const float* dw3 = (const float*)d_in[7];  const float* db3 = (const float*)d_in[8];
    const float* fw1 = (const float*)d_in[9];  const float* fb1 = (const float*)d_in[10];
    const float* fw2 = (const float*)d_in[11]; const float* fb2 = (const float*)d_in[12];
    const float* fw3 = (const float*)d_in[13]; const float* fb3 = (const float*)d_in[14];
    const float* Wda = (const float*)d_in[15]; const float* bda = (const float*)d_in[16];
    const float* Wfa = (const float*)d_in[17]; const float* bfa = (const float*)d_in[18];
    const float* Watt= (const float*)d_in[19]; const float* batt= (const float*)d_in[20];
    const float* W1  = (const float*)d_in[21]; const float* b1  = (const float*)d_in[22];
    const float* W2  = (const float*)d_in[23]; const float* b2  = (const float*)d_in[24];
    const float* W3  = (const float*)d_in[25]; const float* b3  = (const float*)d_in[26];
    const float* Wo  = (const float*)d_in[27]; const float* bo  = (const float*)d_in[28];
    float* out = (float*)d_out;

    __half *x,*h1,*h2,*dc,*att,*hf1,*hf2,*fnn,*pair,*fh1,*fh2;
    __half *w1r,*w2r,*w3r,*fwm2,*fwm3,*WdaH,*WfaH,*WattH,*W1H,*W2H,*W3H;
    float *Am,*fatt,*fh3,*fwm1;
    GADDR(x, g_x); GADDR(h1, g_h1); GADDR(h2, g_h2);
    GADDR(dc, g_dc); GADDR(att, g_att);
    GADDR(hf1, g_hf1); GADDR(hf2, g_hf2); GADDR(fnn, g_fnn);
    GADDR(pair, g_pair); GADDR(fh1, g_fh1); GADDR(fh2, g_fh2);
    GADDR(w1r, g_w1r); GADDR(w2r, g_w2r); GADDR(w3r, g_w3r);
    GADDR(fwm2, g_fwm2); GADDR(fwm3, g_fwm3);
    GADDR(WdaH, g_Wda); GADDR(WfaH, g_Wfa); GADDR(WattH, g_Watt);
    GADDR(W1H, g_W1); GADDR(W2H, g_W2); GADDR(W3H, g_W3);
    GADDR(Am, g_Am); GADDR(fatt, g_fatt); GADDR(fh3, g_fh3); GADDR(fwm1, g_fwm1);

    cudaFuncSetAttribute(gemm2<0,0>, cudaFuncAttributeMaxDynamicSharedMemorySize, GSMEM);
    cudaFuncSetAttribute(gemm2<1,1>, cudaFuncAttributeMaxDynamicSharedMemorySize, GSMEM);
    cudaFuncSetAttribute(gemm2<3,1>, cudaFuncAttributeMaxDynamicSharedMemorySize, GSMEM);
    cudaFuncSetAttribute(gemmS<0,0>, cudaFuncAttributeMaxDynamicSharedMemorySize, SSMEM);
    cudaFuncSetAttribute(gemmS<1,1>, cudaFuncAttributeMaxDynamicSharedMemorySize, SSMEM);
    cudaFuncSetAttribute(gemmS<2,1>, cudaFuncAttributeMaxDynamicSharedMemorySize, SSMEM);
    cudaFuncSetAttribute(gemmS<2,0>, cudaFuncAttributeMaxDynamicSharedMemorySize, SSMEM);

    // prep (launch 5 = conv1 GEMM for ncu -s 5)
    embed_h<<<(BATCH * LD * 32 + 255) / 256, 256>>>(drug, emb, x);                      // 0
    reorder_w_h<<<(128 * 128 * 4 + 255) / 256, 256>>>(dw1, w1r, 128, 128, 4);           // 1
    reorder_w_h<<<(256 * 128 * 6 + 255) / 256, 256>>>(dw2, w2r, 256, 128, 6);           // 2
    reorder_w_h<<<(512 * 256 * 8 + 255) / 256, 256>>>(dw3, w3r, 512, 256, 8);           // 3
    midtap_f32<<<(128 * 7 + 255) / 256, 256>>>(fw1, fwm1, 128 * 7);                     // 4

    // drug conv stack
    gemmS<1,1><<<dim3(1, (BATCH * L1O) / 128), 256, SSMEM>>>(x, w1r, db1,               // 5 (ncu)
        nullptr, nullptr, h1, 128, 512, L1O, (long)LD * 128, 128L, 1);
    gemm2<1,1><<<dim3(2, (BATCH * L2O) / 256), 256, GSMEM>>>(h1, w2r, db2,
        nullptr, nullptr, h2, 256, 768, L2O, (long)L1O * 128, 128L, 1);
    gemm2<1,1><<<dim3(4, (BATCH * L3O) / 256), 256, GSMEM>>>(h2, w3r, db3,
        nullptr, nullptr, dc, 512, 2048, L3O, (long)L2O * 256, 256L, 1);

    // feature branch
    midtap_h<<<(256 * 128 + 255) / 256, 256>>>(fw2, fwm2, 256 * 128);
    midtap_h<<<(512 * 256 + 255) / 256, 256>>>(fw3, fwm3, 512 * 256);
    conv_h<<<(512 * 512 + 255) / 256, 256>>>(Wda, WdaH, 512 * 512);
    conv_h<<<(512 * 512 + 255) / 256, 256>>>(Wfa, WfaH, 512 * 512);
    conv_h<<<(512 * 512 + 255) / 256, 256>>>(Watt, WattH, 512 * 512);

    feat1_k<<<(BATCH * 128) / 256, 256>>>(feature, fwm1, fb1, hf1);
    gemmS<1,1><<<dim3(2, BATCH / 128), 256, SSMEM>>>(hf1, fwm2, fb2,
        nullptr, nullptr, hf2, 256, 128, BATCH, 0L, 128L, 1);
    gemmS<1,1><<<dim3(4, BATCH / 128), 256, SSMEM>>>(hf2, fwm3, fb3,
        nullptr, nullptr, fnn, 512, 256, BATCH, 0L, 256L, 1);
    gemmS<0,0><<<dim3(4, BATCH / 128), 256, SSMEM>>>(fnn, WfaH, bfa,
        nullptr, fatt, nullptr, 512, 512, BATCH, 0L, 512L, 1);

    // s = relu(dc @ Wda^T + bda + fatt[b]) fused
    gemm2<3,1><<<dim3(4, (BATCH * L3O) / 256), 256, GSMEM>>>(dc, WdaH, bda,
        fatt, nullptr, att, 512, 512, BATCH * L3O, 0L, 512L, L3O);

    // A = s @ Watt^T + batt (fp32 out)
    gemm2<0,0><<<dim3(4, (BATCH * L3O) / 256), 256, GSMEM>>>(att, WattH, batt,
        nullptr, Am, nullptr, 512, 512, BATCH * L3O, 0L, 512L, 1);

    reduce_k<<<BATCH, 512>>>(dc, Am, fnn, pair);

    // FC head
    conv_h<<<(1024 * 1024 + 255) / 256, 256>>>(W1, W1H, 1024 * 1024);
    conv_h<<<(1024 * 1024 + 255) / 256, 256>>>(W2, W2H, 1024 * 1024);
    conv_h<<<(512 * 1024 + 255) / 256, 256>>>(W3, W3H, 512 * 1024);

    gemmS<2,1><<<dim3(8, BATCH / 128), 256, SSMEM>>>(pair, W1H, b1,
        nullptr, nullptr, fh1, 1024, 1024, BATCH, 0L, 1024L, 1);
    gemmS<2,1><<<dim3(8, BATCH / 128), 256, SSMEM>>>(fh1, W2H, b2,
        nullptr, nullptr, fh2, 1024, 1024, BATCH, 0L, 1024L, 1);
    gemmS<2,0><<<dim3(4, BATCH / 128), 256, SSMEM>>>(fh2, W3H, b3,
        nullptr, fh3, nullptr, 512, 1024, BATCH, 0L, 1024L, 1);

    final_k<<<BATCH, 128>>>(fh3, Wo, bo, out);
}